// round 9
// baseline (speedup 1.0000x reference)
#include <cuda_runtime.h>
#include <cuda_bf16.h>
#include <math.h>

// Problem constants
#define Bsz 4096
#define Ssz 1536
#define Lsz 2048
#define Hsz 1024
#define MINTOK 460                     // int(0.3*1536)
#define NEEDFIX_THRESH (Ssz - MINTOK)  // 1076

// ---------------- scratch (device globals; no allocations allowed) ----------
__device__ float g_A [(size_t)Bsz * Lsz];
__device__ float g_Bf[(size_t)Bsz * Lsz];
__device__ float g_C1[(size_t)Bsz * Hsz];
__device__ float g_C2[(size_t)Bsz * Hsz];
__device__ float g_C3[(size_t)Bsz * Hsz];
__device__ float g_D1[(size_t)Bsz * (Hsz/2)];
__device__ float g_D2[(size_t)Bsz * (Hsz/4)];

#define CCH 16
__device__ double g_p1[CCH * Lsz];
__device__ double g_p2[CCH * Lsz];
__device__ double g_p3[CCH * Lsz];
__device__ double g_S1[Lsz], g_S2[Lsz], g_S3[Lsz];
__device__ float  g_adj[Lsz];
__device__ float  g_rowEnt[Bsz], g_rowDiff[Bsz];
__device__ double g_cons[1];

// ---- f32x2 packed helpers (PTX-only; each half is an independent IEEE op) --
__device__ __forceinline__ unsigned long long pk2(float lo, float hi) {
    unsigned long long r;
    asm("mov.b64 %0, {%1, %2};" : "=l"(r) : "f"(lo), "f"(hi));
    return r;
}
__device__ __forceinline__ void upk2(unsigned long long v, float& lo, float& hi) {
    asm("mov.b64 {%0, %1}, %2;" : "=f"(lo), "=f"(hi) : "l"(v));
}
__device__ __forceinline__ unsigned long long fma2(unsigned long long a,
                                                   unsigned long long b,
                                                   unsigned long long c) {
    unsigned long long d;
    asm("fma.rn.f32x2 %0, %1, %2, %3;" : "=l"(d) : "l"(a), "l"(b), "l"(c));
    return d;
}

union F4U2 { float4 f; struct { unsigned long long lo, hi; } u; };

// ---------------- GEMM: C[M,N] = A[M,K] @ W[N,K]^T + bias[N] ----------------
// Numerics contract (frozen; outputs bitwise-identical to rounds 6/7/8): per
// output, fp32 FFMA over each ascending 64-k chunk; chunks folded ascending
// into a Kahan (ksum, kcmp) fp32 pair; (ksum+kcmp)+bias at the end. f32x2
// packs two M-adjacent outputs per instruction — identical IEEE arithmetic.
// Perf: 64x64 block tile, 4x4/thread, 256 threads, BK=32 double-buffered
// stages + register prefetch. B is stored in smem PRE-DUPLICATED as (b,b)
// u64 pairs so the inner loop is pure LDS + FFMA2 (no packing movs).
// Smem = 48KB static exactly; ~100 regs -> 2 CTAs/SM.
__global__ void __launch_bounds__(256)
sgemm_nt(const float* __restrict__ A, const float* __restrict__ W,
         const float* __restrict__ bias, float* __restrict__ C,
         int M, int N, int K)
{
    constexpr int BK = 32;
    __shared__ float As[2][BK][64];                    // 16 KB
    __shared__ unsigned long long Bs[2][BK][64];       // 32 KB (dup'd pairs)
    const int tid = threadIdx.x;
    const int bm = blockIdx.y * 64;
    const int bn = blockIdx.x * 64;
    const int tr = (tid >> 4) << 2;     // 0..60 step 4 (C row offset)
    const int tc = (tid & 15) << 2;     // 0..60 step 4 (C col offset)

    const int lrow = tid & 63;          // tile row for loads
    const int lk   = (tid >> 6) << 3;   // 0,8,16,24 (k offset, 8 wide)

    const float* Ap = A + (size_t)(bm + lrow) * K + lk;
    const float* Wp = W + (size_t)(bn + lrow) * K + lk;

    unsigned long long facc2[2][4];     // M-pairs (tr+2p, tr+2p+1) x 4 N
    float ksum[4][4], kcmp[4][4];
#pragma unroll
    for (int i = 0; i < 4; i++)
#pragma unroll
        for (int j = 0; j < 4; j++) { ksum[i][j] = 0.f; kcmp[i][j] = 0.f; }
#pragma unroll
    for (int p = 0; p < 2; p++)
#pragma unroll
        for (int j = 0; j < 4; j++) facc2[p][j] = 0ull;

    const int nch = K / BK;   // 32-k stages; Kahan fold every 2 stages (64 k)

    // prologue: stage chunk 0
    float4 aq0 = *(const float4*)(Ap);
    float4 aq1 = *(const float4*)(Ap + 4);
    float4 bq0 = *(const float4*)(Wp);
    float4 bq1 = *(const float4*)(Wp + 4);
    As[0][lk + 0][lrow] = aq0.x; As[0][lk + 1][lrow] = aq0.y;
    As[0][lk + 2][lrow] = aq0.z; As[0][lk + 3][lrow] = aq0.w;
    As[0][lk + 4][lrow] = aq1.x; As[0][lk + 5][lrow] = aq1.y;
    As[0][lk + 6][lrow] = aq1.z; As[0][lk + 7][lrow] = aq1.w;
    Bs[0][lk + 0][lrow] = pk2(bq0.x, bq0.x); Bs[0][lk + 1][lrow] = pk2(bq0.y, bq0.y);
    Bs[0][lk + 2][lrow] = pk2(bq0.z, bq0.z); Bs[0][lk + 3][lrow] = pk2(bq0.w, bq0.w);
    Bs[0][lk + 4][lrow] = pk2(bq1.x, bq1.x); Bs[0][lk + 5][lrow] = pk2(bq1.y, bq1.y);
    Bs[0][lk + 6][lrow] = pk2(bq1.z, bq1.z); Bs[0][lk + 7][lrow] = pk2(bq1.w, bq1.w);
    __syncthreads();

    for (int c = 0; c < nch; c++) {
        const int buf = c & 1;
        const bool more = (c + 1 < nch);
        if (more) {
            const int k0 = (c + 1) * BK;
            aq0 = *(const float4*)(Ap + k0);
            aq1 = *(const float4*)(Ap + k0 + 4);
            bq0 = *(const float4*)(Wp + k0);
            bq1 = *(const float4*)(Wp + k0 + 4);
        }

#pragma unroll
        for (int k = 0; k < BK; k++) {
            F4U2 a;
            a.f = *(const float4*)(&As[buf][k][tr]);
            const ulonglong2 bA = *(const ulonglong2*)(&Bs[buf][k][tc]);
            const ulonglong2 bB = *(const ulonglong2*)(&Bs[buf][k][tc + 2]);
            facc2[0][0] = fma2(a.u.lo, bA.x, facc2[0][0]);
            facc2[0][1] = fma2(a.u.lo, bA.y, facc2[0][1]);
            facc2[0][2] = fma2(a.u.lo, bB.x, facc2[0][2]);
            facc2[0][3] = fma2(a.u.lo, bB.y, facc2[0][3]);
            facc2[1][0] = fma2(a.u.hi, bA.x, facc2[1][0]);
            facc2[1][1] = fma2(a.u.hi, bA.y, facc2[1][1]);
            facc2[1][2] = fma2(a.u.hi, bB.x, facc2[1][2]);
            facc2[1][3] = fma2(a.u.hi, bB.y, facc2[1][3]);
        }

        if ((c & 1) == 1) {
            // Kahan fold of the completed 64-k chunk into (ksum, kcmp)
#pragma unroll
            for (int p = 0; p < 2; p++)
#pragma unroll
                for (int j = 0; j < 4; j++) {
                    float flo, fhi;
                    upk2(facc2[p][j], flo, fhi);
                    {
                        const int i = 2 * p;
                        const float t = __fadd_rn(ksum[i][j], flo);
                        const float e = __fadd_rn(__fsub_rn(ksum[i][j], t), flo);
                        kcmp[i][j] = __fadd_rn(kcmp[i][j], e);
                        ksum[i][j] = t;
                    }
                    {
                        const int i = 2 * p + 1;
                        const float t = __fadd_rn(ksum[i][j], fhi);
                        const float e = __fadd_rn(__fsub_rn(ksum[i][j], t), fhi);
                        kcmp[i][j] = __fadd_rn(kcmp[i][j], e);
                        ksum[i][j] = t;
                    }
                    facc2[p][j] = 0ull;
                }
        }

        if (more) {
            __syncthreads();
            const int nb = buf ^ 1;
            As[nb][lk + 0][lrow] = aq0.x; As[nb][lk + 1][lrow] = aq0.y;
            As[nb][lk + 2][lrow] = aq0.z; As[nb][lk + 3][lrow] = aq0.w;
            As[nb][lk + 4][lrow] = aq1.x; As[nb][lk + 5][lrow] = aq1.y;
            As[nb][lk + 6][lrow] = aq1.z; As[nb][lk + 7][lrow] = aq1.w;
            Bs[nb][lk + 0][lrow] = pk2(bq0.x, bq0.x); Bs[nb][lk + 1][lrow] = pk2(bq0.y, bq0.y);
            Bs[nb][lk + 2][lrow] = pk2(bq0.z, bq0.z); Bs[nb][lk + 3][lrow] = pk2(bq0.w, bq0.w);
            Bs[nb][lk + 4][lrow] = pk2(bq1.x, bq1.x); Bs[nb][lk + 5][lrow] = pk2(bq1.y, bq1.y);
            Bs[nb][lk + 6][lrow] = pk2(bq1.z, bq1.z); Bs[nb][lk + 7][lrow] = pk2(bq1.w, bq1.w);
            __syncthreads();
        }
    }

    float bj[4];
#pragma unroll
    for (int j = 0; j < 4; j++) bj[j] = bias[bn + tc + j];
#pragma unroll
    for (int i = 0; i < 4; i++) {
        float* Cp = C + (size_t)(bm + tr + i) * N + bn + tc;
        float4 v;
        v.x = __fadd_rn(__fadd_rn(ksum[i][0], kcmp[i][0]), bj[0]);
        v.y = __fadd_rn(__fadd_rn(ksum[i][1], kcmp[i][1]), bj[1]);
        v.z = __fadd_rn(__fadd_rn(ksum[i][2], kcmp[i][2]), bj[2]);
        v.w = __fadd_rn(__fadd_rn(ksum[i][3], kcmp[i][3]), bj[3]);
        *(float4*)Cp = v;
    }
}

// ---------------- LN of padded int input -> X0 (double-precise stats) -------
__global__ void ln_input_kernel(const int* __restrict__ ids,
                                const float* __restrict__ gam,
                                const float* __restrict__ bet,
                                float* __restrict__ out)
{
    __shared__ float s[Lsz];
    __shared__ double red[256];
    const int r = blockIdx.x, tid = threadIdx.x;
    for (int j = tid; j < Lsz; j += 256)
        s[j] = (j < Ssz) ? (float)ids[(size_t)r * Ssz + j] : 0.f;
    __syncthreads();
    double p = 0.0;
    for (int j = tid; j < Lsz; j += 256) p += (double)s[j];
    red[tid] = p; __syncthreads();
    for (int o = 128; o > 0; o >>= 1) { if (tid < o) red[tid] += red[tid + o]; __syncthreads(); }
    const double mean = red[0] / (double)Lsz;
    const float  mf   = (float)mean;
    __syncthreads();
    double v = 0.0;
    for (int j = tid; j < Lsz; j += 256) { double d = (double)s[j] - mean; v += d * d; }
    red[tid] = v; __syncthreads();
    for (int o = 128; o > 0; o >>= 1) { if (tid < o) red[tid] += red[tid + o]; __syncthreads(); }
    const float vf  = (float)(red[0] / (double)Lsz);
    const float arg = __fadd_rn(vf, 1e-5f);
    const float rs  = (float)(1.0 / sqrt((double)arg));
    for (int j = tid; j < Lsz; j += 256) {
        float t = __fmul_rn(__fmul_rn(__fsub_rn(s[j], mf), rs), gam[j]);
        out[(size_t)r * Lsz + j] = __fadd_rn(t, bet[j]);
    }
}

// ---------------- LN + exact GELU (+ optional residual), per row ------------
__global__ void ln_gelu_kernel(const float* __restrict__ in,
                               const float* __restrict__ gam,
                               const float* __restrict__ bet,
                               const float* __restrict__ res,
                               float* __restrict__ out, int n)
{
    __shared__ float s[Lsz];
    __shared__ double red[256];
    const int r = blockIdx.x, tid = threadIdx.x;
    for (int j = tid; j < n; j += 256) s[j] = in[(size_t)r * n + j];
    __syncthreads();
    double p = 0.0;
    for (int j = tid; j < n; j += 256) p += (double)s[j];
    red[tid] = p; __syncthreads();
    for (int o = 128; o > 0; o >>= 1) { if (tid < o) red[tid] += red[tid + o]; __syncthreads(); }
    const double mean = red[0] / (double)n;
    const float  mf   = (float)mean;
    __syncthreads();
    double v = 0.0;
    for (int j = tid; j < n; j += 256) { double d = (double)s[j] - mean; v += d * d; }
    red[tid] = v; __syncthreads();
    for (int o = 128; o > 0; o >>= 1) { if (tid < o) red[tid] += red[tid + o]; __syncthreads(); }
    const float vf  = (float)(red[0] / (double)n);
    const float arg = __fadd_rn(vf, 1e-5f);
    const float rs  = (float)(1.0 / sqrt((double)arg));
    for (int j = tid; j < n; j += 256) {
        float x = __fadd_rn(__fmul_rn(__fmul_rn(__fsub_rn(s[j], mf), rs), gam[j]), bet[j]);
        float u = __fmul_rn(x, 0.70710678118654752f);
        float e = erff(u);
        float ge = __fmul_rn(__fmul_rn(x, __fadd_rn(e, 1.f)), 0.5f);
        float o = res ? __fadd_rn(ge, res[(size_t)r * n + j]) : ge;
        out[(size_t)r * n + j] = o;
    }
}

// ---------------- mu -> z = sigmoid(clip(mu,-5,5)), exact -------------------
__global__ void sigmoid_kernel(const float* __restrict__ mu, float* __restrict__ z)
{
    size_t i = (size_t)blockIdx.x * 256 + threadIdx.x;
    if (i < (size_t)Bsz * Lsz) {
        float m = mu[i];
        m = fminf(5.f, fmaxf(-5.f, m));
        z[i] = (float)(1.0 / (1.0 + exp(-(double)m)));
    }
}

// ---------------- column stats ----------------------------------------------
__global__ void colstats_kernel(const float* __restrict__ Z)
{
    const int j  = blockIdx.x * 256 + threadIdx.x;
    const int ch = blockIdx.y;
    const int r0 = ch * (Bsz / CCH);
    const bool hasN = (j < Lsz - 1);
    double s1 = 0, s2 = 0, s3 = 0;
    for (int r = r0; r < r0 + (Bsz / CCH); ++r) {
        float z  = Z[(size_t)r * Lsz + j];
        float zn = hasN ? Z[(size_t)r * Lsz + j + 1] : 0.f;
        s1 += (double)z;
        s2 += (double)z * (double)z;
        s3 += (double)z * (double)zn;
    }
    g_p1[ch * Lsz + j] = s1;
    g_p2[ch * Lsz + j] = s2;
    g_p3[ch * Lsz + j] = s3;
}

__global__ void colcombine_kernel()
{
    const int j = blockIdx.x * 256 + threadIdx.x;
    double s1 = 0, s2 = 0, s3 = 0;
    for (int c = 0; c < CCH; c++) {
        s1 += g_p1[c * Lsz + j];
        s2 += g_p2[c * Lsz + j];
        s3 += g_p3[c * Lsz + j];
    }
    g_S1[j] = s1; g_S2[j] = s2; g_S3[j] = s3;
}

// ---------------- adj (corr>0.5) + consistency term -------------------------
__global__ void adjcons_kernel(const float* __restrict__ fe)
{
    __shared__ double red[256];
    const int tid = threadIdx.x;
    double cons = 0.0;
    for (int j = tid; j < Lsz; j += 256) {
        double m = g_S1[j] / (double)Bsz;
        cons += fabs(m - (double)fe[j]);
        if (j < Lsz - 1) {
            double cov = g_S3[j] - g_S1[j] * g_S1[j + 1] / (double)Bsz;
            double v1  = g_S2[j]     - g_S1[j]     * g_S1[j]     / (double)Bsz;
            double v2  = g_S2[j + 1] - g_S1[j + 1] * g_S1[j + 1] / (double)Bsz;
            double den = v1 * v2;
            float a = 0.f;
            if (den > 0.0 && cov / sqrt(den) > 0.5) a = 1.f;
            g_adj[j] = a;
        }
    }
    red[tid] = cons; __syncthreads();
    for (int o = 128; o > 0; o >>= 1) { if (tid < o) red[tid] += red[tid + o]; __syncthreads(); }
    if (tid == 0) g_cons[0] = red[0];
}

// ---------------- per-row mask / top-k / outputs -----------------------------
__global__ void __launch_bounds__(256)
rowmask_kernel(const float* __restrict__ Z, const int* __restrict__ ids,
               float* __restrict__ outG, float* __restrict__ outZ)
{
    __shared__ float zs[Lsz];
    __shared__ float redf[256];
    __shared__ int   redi[256];
    __shared__ unsigned int hist[256];
    __shared__ unsigned int sh_prefix;
    __shared__ int sh_k;
    __shared__ int wsum[8];

    const int r = blockIdx.x, tid = threadIdx.x;
    for (int j = tid; j < Lsz; j += 256) zs[j] = Z[(size_t)r * Lsz + j];
    __syncthreads();

    float ent = 0.f, dif = 0.f;
    int cnt = 0;
    for (int j = tid; j < Lsz; j += 256) {
        float p = zs[j];
        ent += -(p * logf(__fadd_rn(p, 1e-7f)) +
                 (1.f - p) * logf(__fadd_rn(__fsub_rn(1.f, p), 1e-7f)));
        if (j < Lsz - 1) dif += fabsf(__fsub_rn(zs[j + 1], zs[j])) * g_adj[j];
        if (j < Ssz) {
            int tok = ids[(size_t)r * Ssz + j];
            if (p < 0.5f && tok != 0) cnt++;
        }
    }
    redf[tid] = ent; __syncthreads();
    for (int o = 128; o > 0; o >>= 1) { if (tid < o) redf[tid] += redf[tid + o]; __syncthreads(); }
    if (tid == 0) g_rowEnt[r] = redf[0];
    __syncthreads();
    redf[tid] = dif; __syncthreads();
    for (int o = 128; o > 0; o >>= 1) { if (tid < o) redf[tid] += redf[tid + o]; __syncthreads(); }
    if (tid == 0) g_rowDiff[r] = redf[0];
    __syncthreads();
    redi[tid] = cnt; __syncthreads();
    for (int o = 128; o > 0; o >>= 1) { if (tid < o) redi[tid] += redi[tid + o]; __syncthreads(); }
    const int total = redi[0];
    __syncthreads();
    const bool needfix = total > NEEDFIX_THRESH;

    unsigned int tsel = 0;
    int nEqKeep = 0;
    if (needfix) {
        unsigned int prefix = 0, highmask = 0;
        int k = MINTOK;
        for (int pass = 0; pass < 4; pass++) {
            const int shift = 24 - 8 * pass;
            hist[tid] = 0;
            __syncthreads();
            for (int j = tid; j < Ssz; j += 256) {
                unsigned int key = __float_as_uint(zs[j]);
                if ((key & highmask) == prefix)
                    atomicAdd(&hist[(key >> shift) & 0xFFu], 1u);
            }
            __syncthreads();
            if (tid == 0) {
                int cum = 0, b = 255;
                for (; b >= 0; --b) { cum += (int)hist[b]; if (cum >= k) break; }
                sh_k = k - (cum - (int)hist[b]);
                sh_prefix = prefix | ((unsigned int)b << shift);
            }
            __syncthreads();
            prefix = sh_prefix;
            k = sh_k;
            highmask |= 0xFFu << shift;
            __syncthreads();
        }
        tsel = prefix;
        int cg = 0;
        for (int j = tid; j < Ssz; j += 256)
            if (__float_as_uint(zs[j]) > tsel) cg++;
        redi[tid] = cg; __syncthreads();
        for (int o = 128; o > 0; o >>= 1) { if (tid < o) redi[tid] += redi[tid + o]; __syncthreads(); }
        nEqKeep = MINTOK - redi[0];
        __syncthreads();
    }

    int runEq = 0;
    for (int base = 0; base < Ssz; base += 256) {
        const int j = base + tid;
        const float zv = zs[j];
        const int tok = ids[(size_t)r * Ssz + j];
        bool m = (zv < 0.5f) && (tok != 0);
        if (needfix) {
            const unsigned int key = __float_as_uint(zv);
            const int eq = (key == tsel) ? 1 : 0;
            const unsigned int bal = __ballot_sync(0xffffffffu, eq);
            const int lane = tid & 31, w = tid >> 5;
            const int wexcl = __popc(bal & ((1u << lane) - 1u));
            if (lane == 31) wsum[w] = __popc(bal);
            __syncthreads();
            int woff = 0;
            for (int i = 0; i < w; i++) woff += wsum[i];
            const int excl = woff + wexcl;
            const bool keep = (key > tsel) || (eq && (runEq + excl) < nEqKeep);
            if (keep) m = false;
            __syncthreads();
            if (tid == 0) { int t = 0; for (int i = 0; i < 8; i++) t += wsum[i]; redi[0] = t; }
            __syncthreads();
            runEq += redi[0];
        }
        if (j == 0) m = false;
        outG[(size_t)r * Ssz + j] = m ? 0.f : (float)tok;
        outZ[(size_t)r * Ssz + j] = zv;
    }
}

// ---------------- final loss scalar -----------------------------------------
__global__ void finalize_kernel(float* __restrict__ out)
{
    __shared__ double red[256];
    const int tid = threadIdx.x;
    double e = 0, d = 0;
    for (int r = tid; r < Bsz; r += 256) {
        e += (double)g_rowEnt[r];
        d += (double)g_rowDiff[r];
    }
    red[tid] = e; __syncthreads();
    for (int o = 128; o > 0; o >>= 1) { if (tid < o) red[tid] += red[tid + o]; __syncthreads(); }
    const double entSum = red[0];
    __syncthreads();
    red[tid] = d; __syncthreads();
    for (int o = 128; o > 0; o >>= 1) { if (tid < o) red[tid] += red[tid + o]; __syncthreads(); }
    const double difSum = red[0];
    if (tid == 0) {
        double R1 = -0.001 * entSum / ((double)Bsz * (double)Lsz);
        double R2 =  0.001 * difSum / ((double)Bsz * (double)(Lsz - 1));
        double cons = 0.001 * g_cons[0] / (double)Lsz;
        out[(size_t)Bsz * Ssz] = (float)(R1 + R2 + cons);
    }
}

// ---------------- launch ------------------------------------------------------
extern "C" void kernel_launch(void* const* d_in, const int* in_sizes, int n_in,
                              void* d_out, int out_size)
{
    const float* in_g  = (const float*)d_in[0];
    const float* in_b  = (const float*)d_in[1];
    const float* wv    = (const float*)d_in[2];
    const float* bv    = (const float*)d_in[3];
    const float* wo    = (const float*)d_in[4];
    const float* bo    = (const float*)d_in[5];
    const float* w2    = (const float*)d_in[6];
    const float* b2    = (const float*)d_in[7];
    const float* g1    = (const float*)d_in[8];
    const float* be1   = (const float*)d_in[9];
    const float* w4    = (const float*)d_in[10];
    const float* b4    = (const float*)d_in[11];
    const float* g3    = (const float*)d_in[12];
    const float* be3   = (const float*)d_in[13];
    const float* w5    = (const float*)d_in[14];
    const float* b5    = (const float*)d_in[15];
    const float* g4    = (const float*)d_in[16];
    const float* be4   = (const float*)d_in[17];
    const float* w6    = (const float*)d_in[18];
    const float* b6    = (const float*)d_in[19];
    const float* g5    = (const float*)d_in[20];
    const float* be5   = (const float*)d_in[21];
    const float* w7    = (const float*)d_in[22];
    const float* b7    = (const float*)d_in[23];
    const float* g6    = (const float*)d_in[24];
    const float* be6   = (const float*)d_in[25];
    const float* wout  = (const float*)d_in[26];
    const float* bout  = (const float*)d_in[27];
    const float* fe    = (const float*)d_in[28];
    const int*   ids   = (const int*)d_in[29];
    float* out = (float*)d_out;

    float *pA, *pBf, *pC1, *pC2, *pC3, *pD1, *pD2;
    cudaGetSymbolAddress((void**)&pA,  g_A);
    cudaGetSymbolAddress((void**)&pBf, g_Bf);
    cudaGetSymbolAddress((void**)&pC1, g_C1);
    cudaGetSymbolAddress((void**)&pC2, g_C2);
    cudaGetSymbolAddress((void**)&pC3, g_C3);
    cudaGetSymbolAddress((void**)&pD1, g_D1);
    cudaGetSymbolAddress((void**)&pD2, g_D2);

    ln_input_kernel<<<Bsz, 256>>>(ids, in_g, in_b, pA);

    sgemm_nt<<<dim3(Lsz/64, Bsz/64), 256>>>(pA,  wv, bv, pBf, Bsz, Lsz, Lsz);
    sgemm_nt<<<dim3(Lsz/64, Bsz/64), 256>>>(pBf, wo, bo, pA,  Bsz, Lsz, Lsz);

    sgemm_nt<<<dim3(Hsz/64, Bsz/64), 256>>>(pA, w2, b2, pC1, Bsz, Hsz, Lsz);
    ln_gelu_kernel<<<Bsz, 256>>>(pC1, g1, be1, pC1, pC2, Hsz);

    sgemm_nt<<<dim3(Hsz/64, Bsz/64), 256>>>(pC2, w4, b4, pC3, Bsz, Hsz, Hsz);
    ln_gelu_kernel<<<Bsz, 256>>>(pC3, g3, be3, nullptr, pC3, Hsz);

    sgemm_nt<<<dim3(Hsz/64, Bsz/64), 256>>>(pC3, w5, b5, pC1, Bsz, Hsz, Hsz);
    ln_gelu_kernel<<<Bsz, 256>>>(pC1, g4, be4, pC2, pC1, Hsz);

    sgemm_nt<<<dim3((Hsz/2)/64, Bsz/64), 256>>>(pC1, w6, b6, pD1, Bsz, Hsz/2, Hsz);
    ln_gelu_kernel<<<Bsz, 256>>>(pD1, g5, be5, nullptr, pD1, Hsz/2);

    sgemm_nt<<<dim3((Hsz/4)/64, Bsz/64), 256>>>(pD1, w7, b7, pD2, Bsz, Hsz/4, Hsz/2);
    ln_gelu_kernel<<<Bsz, 256>>>(pD2, g6, be6, nullptr, pD2, Hsz/4);

    sgemm_nt<<<dim3(Lsz/64, Bsz/64), 256>>>(pD2, wout, bout, pBf, Bsz, Lsz, Hsz/4);
    sigmoid_kernel<<<(Bsz*Lsz)/256, 256>>>(pBf, pA);

    colstats_kernel<<<dim3(Lsz/256, CCH), 256>>>(pA);
    colcombine_kernel<<<Lsz/256, 256>>>();
    adjcons_kernel<<<1, 256>>>(fe);

    rowmask_kernel<<<Bsz, 256>>>(pA, ids, out, out + (size_t)Bsz * Ssz + 1);

    finalize_kernel<<<1, 256>>>(out);
}

// round 10
// speedup vs baseline: 1.7808x; 1.7808x over previous
#include <cuda_runtime.h>
#include <cuda_bf16.h>
#include <math.h>

// Problem constants
#define Bsz 4096
#define Ssz 1536
#define Lsz 2048
#define Hsz 1024
#define MINTOK 460                     // int(0.3*1536)
#define NEEDFIX_THRESH (Ssz - MINTOK)  // 1076

// ---------------- scratch (device globals; no allocations allowed) ----------
__device__ float g_A [(size_t)Bsz * Lsz];
__device__ float g_Bf[(size_t)Bsz * Lsz];
__device__ float g_C1[(size_t)Bsz * Hsz];
__device__ float g_C2[(size_t)Bsz * Hsz];
__device__ float g_C3[(size_t)Bsz * Hsz];
__device__ float g_D1[(size_t)Bsz * (Hsz/2)];
__device__ float g_D2[(size_t)Bsz * (Hsz/4)];

#define CCH 16
__device__ double g_p1[CCH * Lsz];
__device__ double g_p2[CCH * Lsz];
__device__ double g_p3[CCH * Lsz];
__device__ double g_S1[Lsz], g_S2[Lsz], g_S3[Lsz];
__device__ float  g_adj[Lsz];
__device__ float  g_rowEnt[Bsz], g_rowDiff[Bsz];
__device__ double g_cons[1];

// ---- f32x2 packed helpers (PTX-only; each half is an independent IEEE op) --
__device__ __forceinline__ unsigned long long pk2(float lo, float hi) {
    unsigned long long r;
    asm("mov.b64 %0, {%1, %2};" : "=l"(r) : "f"(lo), "f"(hi));
    return r;
}
__device__ __forceinline__ void upk2(unsigned long long v, float& lo, float& hi) {
    asm("mov.b64 {%0, %1}, %2;" : "=f"(lo), "=f"(hi) : "l"(v));
}
__device__ __forceinline__ unsigned long long fma2(unsigned long long a,
                                                   unsigned long long b,
                                                   unsigned long long c) {
    unsigned long long d;
    asm("fma.rn.f32x2 %0, %1, %2, %3;" : "=l"(d) : "l"(a), "l"(b), "l"(c));
    return d;
}

union F4U2 { float4 f; struct { unsigned long long lo, hi; } u; };

// ---------------- GEMM: C[M,N] = A[M,K] @ W[N,K]^T + bias[N] ----------------
// Numerics contract (frozen; outputs bitwise-identical to rounds 6-9): per
// output, fp32 FFMA over each ascending 64-k chunk; chunks folded ascending
// into a Kahan (ksum, kcmp) fp32 pair; (ksum+kcmp)+bias at the end. f32x2
// packs two M-adjacent outputs per instruction — identical IEEE arithmetic.
// Perf: 64x64 block tile, 4x4/thread, 256 threads, BK=32 double-buffered
// stages + register prefetch. B kept as PLAIN floats in smem (16B-stride
// reads, conflict-benign); B duplication into (b,b) pairs happens in
// registers (4 pk2/k, hidden under the FMA-pipe shadow). ~105 regs, 33.5KB
// smem -> 2 CTAs/SM.
__global__ void __launch_bounds__(256)
sgemm_nt(const float* __restrict__ A, const float* __restrict__ W,
         const float* __restrict__ bias, float* __restrict__ C,
         int M, int N, int K)
{
    constexpr int BK = 32;
    __shared__ float As[2][BK][64];       // 16 KB (A reads are broadcast)
    __shared__ float Bs[2][BK][64 + 4];   // 17.4 KB (pad; 16B-stride reads)
    const int tid = threadIdx.x;
    const int bm = blockIdx.y * 64;
    const int bn = blockIdx.x * 64;
    const int tr = (tid >> 4) << 2;     // 0..60 step 4 (C row offset)
    const int tc = (tid & 15) << 2;     // 0..60 step 4 (C col offset)

    const int lrow = tid & 63;          // tile row for loads
    const int lk   = (tid >> 6) << 3;   // 0,8,16,24 (k offset, 8 wide)

    const float* Ap = A + (size_t)(bm + lrow) * K + lk;
    const float* Wp = W + (size_t)(bn + lrow) * K + lk;

    unsigned long long facc2[2][4];     // M-pairs (tr+2p, tr+2p+1) x 4 N
    float ksum[4][4], kcmp[4][4];
#pragma unroll
    for (int i = 0; i < 4; i++)
#pragma unroll
        for (int j = 0; j < 4; j++) { ksum[i][j] = 0.f; kcmp[i][j] = 0.f; }
#pragma unroll
    for (int p = 0; p < 2; p++)
#pragma unroll
        for (int j = 0; j < 4; j++) facc2[p][j] = 0ull;

    const int nch = K / BK;   // 32-k stages; Kahan fold every 2 stages (64 k)

    // prologue: stage chunk 0
    float4 aq0 = *(const float4*)(Ap);
    float4 aq1 = *(const float4*)(Ap + 4);
    float4 bq0 = *(const float4*)(Wp);
    float4 bq1 = *(const float4*)(Wp + 4);
    As[0][lk + 0][lrow] = aq0.x; As[0][lk + 1][lrow] = aq0.y;
    As[0][lk + 2][lrow] = aq0.z; As[0][lk + 3][lrow] = aq0.w;
    As[0][lk + 4][lrow] = aq1.x; As[0][lk + 5][lrow] = aq1.y;
    As[0][lk + 6][lrow] = aq1.z; As[0][lk + 7][lrow] = aq1.w;
    Bs[0][lk + 0][lrow] = bq0.x; Bs[0][lk + 1][lrow] = bq0.y;
    Bs[0][lk + 2][lrow] = bq0.z; Bs[0][lk + 3][lrow] = bq0.w;
    Bs[0][lk + 4][lrow] = bq1.x; Bs[0][lk + 5][lrow] = bq1.y;
    Bs[0][lk + 6][lrow] = bq1.z; Bs[0][lk + 7][lrow] = bq1.w;
    __syncthreads();

    for (int c = 0; c < nch; c++) {
        const int buf = c & 1;
        const bool more = (c + 1 < nch);
        if (more) {
            const int k0 = (c + 1) * BK;
            aq0 = *(const float4*)(Ap + k0);
            aq1 = *(const float4*)(Ap + k0 + 4);
            bq0 = *(const float4*)(Wp + k0);
            bq1 = *(const float4*)(Wp + k0 + 4);
        }

#pragma unroll
        for (int k = 0; k < BK; k++) {
            F4U2 a;
            a.f = *(const float4*)(&As[buf][k][tr]);
            const float4 bv = *(const float4*)(&Bs[buf][k][tc]);
            const unsigned long long bb0 = pk2(bv.x, bv.x);
            const unsigned long long bb1 = pk2(bv.y, bv.y);
            const unsigned long long bb2 = pk2(bv.z, bv.z);
            const unsigned long long bb3 = pk2(bv.w, bv.w);
            facc2[0][0] = fma2(a.u.lo, bb0, facc2[0][0]);
            facc2[0][1] = fma2(a.u.lo, bb1, facc2[0][1]);
            facc2[0][2] = fma2(a.u.lo, bb2, facc2[0][2]);
            facc2[0][3] = fma2(a.u.lo, bb3, facc2[0][3]);
            facc2[1][0] = fma2(a.u.hi, bb0, facc2[1][0]);
            facc2[1][1] = fma2(a.u.hi, bb1, facc2[1][1]);
            facc2[1][2] = fma2(a.u.hi, bb2, facc2[1][2]);
            facc2[1][3] = fma2(a.u.hi, bb3, facc2[1][3]);
        }

        if ((c & 1) == 1) {
            // Kahan fold of the completed 64-k chunk into (ksum, kcmp)
#pragma unroll
            for (int p = 0; p < 2; p++)
#pragma unroll
                for (int j = 0; j < 4; j++) {
                    float flo, fhi;
                    upk2(facc2[p][j], flo, fhi);
                    {
                        const int i = 2 * p;
                        const float t = __fadd_rn(ksum[i][j], flo);
                        const float e = __fadd_rn(__fsub_rn(ksum[i][j], t), flo);
                        kcmp[i][j] = __fadd_rn(kcmp[i][j], e);
                        ksum[i][j] = t;
                    }
                    {
                        const int i = 2 * p + 1;
                        const float t = __fadd_rn(ksum[i][j], fhi);
                        const float e = __fadd_rn(__fsub_rn(ksum[i][j], t), fhi);
                        kcmp[i][j] = __fadd_rn(kcmp[i][j], e);
                        ksum[i][j] = t;
                    }
                    facc2[p][j] = 0ull;
                }
        }

        if (more) {
            __syncthreads();
            const int nb = buf ^ 1;
            As[nb][lk + 0][lrow] = aq0.x; As[nb][lk + 1][lrow] = aq0.y;
            As[nb][lk + 2][lrow] = aq0.z; As[nb][lk + 3][lrow] = aq0.w;
            As[nb][lk + 4][lrow] = aq1.x; As[nb][lk + 5][lrow] = aq1.y;
            As[nb][lk + 6][lrow] = aq1.z; As[nb][lk + 7][lrow] = aq1.w;
            Bs[nb][lk + 0][lrow] = bq0.x; Bs[nb][lk + 1][lrow] = bq0.y;
            Bs[nb][lk + 2][lrow] = bq0.z; Bs[nb][lk + 3][lrow] = bq0.w;
            Bs[nb][lk + 4][lrow] = bq1.x; Bs[nb][lk + 5][lrow] = bq1.y;
            Bs[nb][lk + 6][lrow] = bq1.z; Bs[nb][lk + 7][lrow] = bq1.w;
            __syncthreads();
        }
    }

    float bj[4];
#pragma unroll
    for (int j = 0; j < 4; j++) bj[j] = bias[bn + tc + j];
#pragma unroll
    for (int i = 0; i < 4; i++) {
        float* Cp = C + (size_t)(bm + tr + i) * N + bn + tc;
        float4 v;
        v.x = __fadd_rn(__fadd_rn(ksum[i][0], kcmp[i][0]), bj[0]);
        v.y = __fadd_rn(__fadd_rn(ksum[i][1], kcmp[i][1]), bj[1]);
        v.z = __fadd_rn(__fadd_rn(ksum[i][2], kcmp[i][2]), bj[2]);
        v.w = __fadd_rn(__fadd_rn(ksum[i][3], kcmp[i][3]), bj[3]);
        *(float4*)Cp = v;
    }
}

// ---------------- LN of padded int input -> X0 (double-precise stats) -------
__global__ void ln_input_kernel(const int* __restrict__ ids,
                                const float* __restrict__ gam,
                                const float* __restrict__ bet,
                                float* __restrict__ out)
{
    __shared__ float s[Lsz];
    __shared__ double red[256];
    const int r = blockIdx.x, tid = threadIdx.x;
    for (int j = tid; j < Lsz; j += 256)
        s[j] = (j < Ssz) ? (float)ids[(size_t)r * Ssz + j] : 0.f;
    __syncthreads();
    double p = 0.0;
    for (int j = tid; j < Lsz; j += 256) p += (double)s[j];
    red[tid] = p; __syncthreads();
    for (int o = 128; o > 0; o >>= 1) { if (tid < o) red[tid] += red[tid + o]; __syncthreads(); }
    const double mean = red[0] / (double)Lsz;
    const float  mf   = (float)mean;
    __syncthreads();
    double v = 0.0;
    for (int j = tid; j < Lsz; j += 256) { double d = (double)s[j] - mean; v += d * d; }
    red[tid] = v; __syncthreads();
    for (int o = 128; o > 0; o >>= 1) { if (tid < o) red[tid] += red[tid + o]; __syncthreads(); }
    const float vf  = (float)(red[0] / (double)Lsz);
    const float arg = __fadd_rn(vf, 1e-5f);
    const float rs  = (float)(1.0 / sqrt((double)arg));
    for (int j = tid; j < Lsz; j += 256) {
        float t = __fmul_rn(__fmul_rn(__fsub_rn(s[j], mf), rs), gam[j]);
        out[(size_t)r * Lsz + j] = __fadd_rn(t, bet[j]);
    }
}

// ---------------- LN + exact GELU (+ optional residual), per row ------------
__global__ void ln_gelu_kernel(const float* __restrict__ in,
                               const float* __restrict__ gam,
                               const float* __restrict__ bet,
                               const float* __restrict__ res,
                               float* __restrict__ out, int n)
{
    __shared__ float s[Lsz];
    __shared__ double red[256];
    const int r = blockIdx.x, tid = threadIdx.x;
    for (int j = tid; j < n; j += 256) s[j] = in[(size_t)r * n + j];
    __syncthreads();
    double p = 0.0;
    for (int j = tid; j < n; j += 256) p += (double)s[j];
    red[tid] = p; __syncthreads();
    for (int o = 128; o > 0; o >>= 1) { if (tid < o) red[tid] += red[tid + o]; __syncthreads(); }
    const double mean = red[0] / (double)n;
    const float  mf   = (float)mean;
    __syncthreads();
    double v = 0.0;
    for (int j = tid; j < n; j += 256) { double d = (double)s[j] - mean; v += d * d; }
    red[tid] = v; __syncthreads();
    for (int o = 128; o > 0; o >>= 1) { if (tid < o) red[tid] += red[tid + o]; __syncthreads(); }
    const float vf  = (float)(red[0] / (double)n);
    const float arg = __fadd_rn(vf, 1e-5f);
    const float rs  = (float)(1.0 / sqrt((double)arg));
    for (int j = tid; j < n; j += 256) {
        float x = __fadd_rn(__fmul_rn(__fmul_rn(__fsub_rn(s[j], mf), rs), gam[j]), bet[j]);
        float u = __fmul_rn(x, 0.70710678118654752f);
        float e = erff(u);
        float ge = __fmul_rn(__fmul_rn(x, __fadd_rn(e, 1.f)), 0.5f);
        float o = res ? __fadd_rn(ge, res[(size_t)r * n + j]) : ge;
        out[(size_t)r * n + j] = o;
    }
}

// ---------------- mu -> z = sigmoid(clip(mu,-5,5)), exact -------------------
__global__ void sigmoid_kernel(const float* __restrict__ mu, float* __restrict__ z)
{
    size_t i = (size_t)blockIdx.x * 256 + threadIdx.x;
    if (i < (size_t)Bsz * Lsz) {
        float m = mu[i];
        m = fminf(5.f, fmaxf(-5.f, m));
        z[i] = (float)(1.0 / (1.0 + exp(-(double)m)));
    }
}

// ---------------- column stats ----------------------------------------------
__global__ void colstats_kernel(const float* __restrict__ Z)
{
    const int j  = blockIdx.x * 256 + threadIdx.x;
    const int ch = blockIdx.y;
    const int r0 = ch * (Bsz / CCH);
    const bool hasN = (j < Lsz - 1);
    double s1 = 0, s2 = 0, s3 = 0;
    for (int r = r0; r < r0 + (Bsz / CCH); ++r) {
        float z  = Z[(size_t)r * Lsz + j];
        float zn = hasN ? Z[(size_t)r * Lsz + j + 1] : 0.f;
        s1 += (double)z;
        s2 += (double)z * (double)z;
        s3 += (double)z * (double)zn;
    }
    g_p1[ch * Lsz + j] = s1;
    g_p2[ch * Lsz + j] = s2;
    g_p3[ch * Lsz + j] = s3;
}

__global__ void colcombine_kernel()
{
    const int j = blockIdx.x * 256 + threadIdx.x;
    double s1 = 0, s2 = 0, s3 = 0;
    for (int c = 0; c < CCH; c++) {
        s1 += g_p1[c * Lsz + j];
        s2 += g_p2[c * Lsz + j];
        s3 += g_p3[c * Lsz + j];
    }
    g_S1[j] = s1; g_S2[j] = s2; g_S3[j] = s3;
}

// ---------------- adj (corr>0.5) + consistency term -------------------------
__global__ void adjcons_kernel(const float* __restrict__ fe)
{
    __shared__ double red[256];
    const int tid = threadIdx.x;
    double cons = 0.0;
    for (int j = tid; j < Lsz; j += 256) {
        double m = g_S1[j] / (double)Bsz;
        cons += fabs(m - (double)fe[j]);
        if (j < Lsz - 1) {
            double cov = g_S3[j] - g_S1[j] * g_S1[j + 1] / (double)Bsz;
            double v1  = g_S2[j]     - g_S1[j]     * g_S1[j]     / (double)Bsz;
            double v2  = g_S2[j + 1] - g_S1[j + 1] * g_S1[j + 1] / (double)Bsz;
            double den = v1 * v2;
            float a = 0.f;
            if (den > 0.0 && cov / sqrt(den) > 0.5) a = 1.f;
            g_adj[j] = a;
        }
    }
    red[tid] = cons; __syncthreads();
    for (int o = 128; o > 0; o >>= 1) { if (tid < o) red[tid] += red[tid + o]; __syncthreads(); }
    if (tid == 0) g_cons[0] = red[0];
}

// ---------------- per-row mask / top-k / outputs -----------------------------
__global__ void __launch_bounds__(256)
rowmask_kernel(const float* __restrict__ Z, const int* __restrict__ ids,
               float* __restrict__ outG, float* __restrict__ outZ)
{
    __shared__ float zs[Lsz];
    __shared__ float redf[256];
    __shared__ int   redi[256];
    __shared__ unsigned int hist[256];
    __shared__ unsigned int sh_prefix;
    __shared__ int sh_k;
    __shared__ int wsum[8];

    const int r = blockIdx.x, tid = threadIdx.x;
    for (int j = tid; j < Lsz; j += 256) zs[j] = Z[(size_t)r * Lsz + j];
    __syncthreads();

    float ent = 0.f, dif = 0.f;
    int cnt = 0;
    for (int j = tid; j < Lsz; j += 256) {
        float p = zs[j];
        ent += -(p * logf(__fadd_rn(p, 1e-7f)) +
                 (1.f - p) * logf(__fadd_rn(__fsub_rn(1.f, p), 1e-7f)));
        if (j < Lsz - 1) dif += fabsf(__fsub_rn(zs[j + 1], zs[j])) * g_adj[j];
        if (j < Ssz) {
            int tok = ids[(size_t)r * Ssz + j];
            if (p < 0.5f && tok != 0) cnt++;
        }
    }
    redf[tid] = ent; __syncthreads();
    for (int o = 128; o > 0; o >>= 1) { if (tid < o) redf[tid] += redf[tid + o]; __syncthreads(); }
    if (tid == 0) g_rowEnt[r] = redf[0];
    __syncthreads();
    redf[tid] = dif; __syncthreads();
    for (int o = 128; o > 0; o >>= 1) { if (tid < o) redf[tid] += redf[tid + o]; __syncthreads(); }
    if (tid == 0) g_rowDiff[r] = redf[0];
    __syncthreads();
    redi[tid] = cnt; __syncthreads();
    for (int o = 128; o > 0; o >>= 1) { if (tid < o) redi[tid] += redi[tid + o]; __syncthreads(); }
    const int total = redi[0];
    __syncthreads();
    const bool needfix = total > NEEDFIX_THRESH;

    unsigned int tsel = 0;
    int nEqKeep = 0;
    if (needfix) {
        unsigned int prefix = 0, highmask = 0;
        int k = MINTOK;
        for (int pass = 0; pass < 4; pass++) {
            const int shift = 24 - 8 * pass;
            hist[tid] = 0;
            __syncthreads();
            for (int j = tid; j < Ssz; j += 256) {
                unsigned int key = __float_as_uint(zs[j]);
                if ((key & highmask) == prefix)
                    atomicAdd(&hist[(key >> shift) & 0xFFu], 1u);
            }
            __syncthreads();
            if (tid == 0) {
                int cum = 0, b = 255;
                for (; b >= 0; --b) { cum += (int)hist[b]; if (cum >= k) break; }
                sh_k = k - (cum - (int)hist[b]);
                sh_prefix = prefix | ((unsigned int)b << shift);
            }
            __syncthreads();
            prefix = sh_prefix;
            k = sh_k;
            highmask |= 0xFFu << shift;
            __syncthreads();
        }
        tsel = prefix;
        int cg = 0;
        for (int j = tid; j < Ssz; j += 256)
            if (__float_as_uint(zs[j]) > tsel) cg++;
        redi[tid] = cg; __syncthreads();
        for (int o = 128; o > 0; o >>= 1) { if (tid < o) redi[tid] += redi[tid + o]; __syncthreads(); }
        nEqKeep = MINTOK - redi[0];
        __syncthreads();
    }

    int runEq = 0;
    for (int base = 0; base < Ssz; base += 256) {
        const int j = base + tid;
        const float zv = zs[j];
        const int tok = ids[(size_t)r * Ssz + j];
        bool m = (zv < 0.5f) && (tok != 0);
        if (needfix) {
            const unsigned int key = __float_as_uint(zv);
            const int eq = (key == tsel) ? 1 : 0;
            const unsigned int bal = __ballot_sync(0xffffffffu, eq);
            const int lane = tid & 31, w = tid >> 5;
            const int wexcl = __popc(bal & ((1u << lane) - 1u));
            if (lane == 31) wsum[w] = __popc(bal);
            __syncthreads();
            int woff = 0;
            for (int i = 0; i < w; i++) woff += wsum[i];
            const int excl = woff + wexcl;
            const bool keep = (key > tsel) || (eq && (runEq + excl) < nEqKeep);
            if (keep) m = false;
            __syncthreads();
            if (tid == 0) { int t = 0; for (int i = 0; i < 8; i++) t += wsum[i]; redi[0] = t; }
            __syncthreads();
            runEq += redi[0];
        }
        if (j == 0) m = false;
        outG[(size_t)r * Ssz + j] = m ? 0.f : (float)tok;
        outZ[(size_t)r * Ssz + j] = zv;
    }
}

// ---------------- final loss scalar -----------------------------------------
__global__ void finalize_kernel(float* __restrict__ out)
{
    __shared__ double red[256];
    const int tid = threadIdx.x;
    double e = 0, d = 0;
    for (int r = tid; r < Bsz; r += 256) {
        e += (double)g_rowEnt[r];
        d += (double)g_rowDiff[r];
    }
    red[tid] = e; __syncthreads();
    for (int o = 128; o > 0; o >>= 1) { if (tid < o) red[tid] += red[tid + o]; __syncthreads(); }
    const double entSum = red[0];
    __syncthreads();
    red[tid] = d; __syncthreads();
    for (int o = 128; o > 0; o >>= 1) { if (tid < o) red[tid] += red[tid + o]; __syncthreads(); }
    const double difSum = red[0];
    if (tid == 0) {
        double R1 = -0.001 * entSum / ((double)Bsz * (double)Lsz);
        double R2 =  0.001 * difSum / ((double)Bsz * (double)(Lsz - 1));
        double cons = 0.001 * g_cons[0] / (double)Lsz;
        out[(size_t)Bsz * Ssz] = (float)(R1 + R2 + cons);
    }
}

// ---------------- launch ------------------------------------------------------
extern "C" void kernel_launch(void* const* d_in, const int* in_sizes, int n_in,
                              void* d_out, int out_size)
{
    const float* in_g  = (const float*)d_in[0];
    const float* in_b  = (const float*)d_in[1];
    const float* wv    = (const float*)d_in[2];
    const float* bv    = (const float*)d_in[3];
    const float* wo    = (const float*)d_in[4];
    const float* bo    = (const float*)d_in[5];
    const float* w2    = (const float*)d_in[6];
    const float* b2    = (const float*)d_in[7];
    const float* g1    = (const float*)d_in[8];
    const float* be1   = (const float*)d_in[9];
    const float* w4    = (const float*)d_in[10];
    const float* b4    = (const float*)d_in[11];
    const float* g3    = (const float*)d_in[12];
    const float* be3   = (const float*)d_in[13];
    const float* w5    = (const float*)d_in[14];
    const float* b5    = (const float*)d_in[15];
    const float* g4    = (const float*)d_in[16];
    const float* be4   = (const float*)d_in[17];
    const float* w6    = (const float*)d_in[18];
    const float* b6    = (const float*)d_in[19];
    const float* g5    = (const float*)d_in[20];
    const float* be5   = (const float*)d_in[21];
    const float* w7    = (const float*)d_in[22];
    const float* b7    = (const float*)d_in[23];
    const float* g6    = (const float*)d_in[24];
    const float* be6   = (const float*)d_in[25];
    const float* wout  = (const float*)d_in[26];
    const float* bout  = (const float*)d_in[27];
    const float* fe    = (const float*)d_in[28];
    const int*   ids   = (const int*)d_in[29];
    float* out = (float*)d_out;

    float *pA, *pBf, *pC1, *pC2, *pC3, *pD1, *pD2;
    cudaGetSymbolAddress((void**)&pA,  g_A);
    cudaGetSymbolAddress((void**)&pBf, g_Bf);
    cudaGetSymbolAddress((void**)&pC1, g_C1);
    cudaGetSymbolAddress((void**)&pC2, g_C2);
    cudaGetSymbolAddress((void**)&pC3, g_C3);
    cudaGetSymbolAddress((void**)&pD1, g_D1);
    cudaGetSymbolAddress((void**)&pD2, g_D2);

    ln_input_kernel<<<Bsz, 256>>>(ids, in_g, in_b, pA);

    sgemm_nt<<<dim3(Lsz/64, Bsz/64), 256>>>(pA,  wv, bv, pBf, Bsz, Lsz, Lsz);
    sgemm_nt<<<dim3(Lsz/64, Bsz/64), 256>>>(pBf, wo, bo, pA,  Bsz, Lsz, Lsz);

    sgemm_nt<<<dim3(Hsz/64, Bsz/64), 256>>>(pA, w2, b2, pC1, Bsz, Hsz, Lsz);
    ln_gelu_kernel<<<Bsz, 256>>>(pC1, g1, be1, pC1, pC2, Hsz);

    sgemm_nt<<<dim3(Hsz/64, Bsz/64), 256>>>(pC2, w4, b4, pC3, Bsz, Hsz, Hsz);
    ln_gelu_kernel<<<Bsz, 256>>>(pC3, g3, be3, nullptr, pC3, Hsz);

    sgemm_nt<<<dim3(Hsz/64, Bsz/64), 256>>>(pC3, w5, b5, pC1, Bsz, Hsz, Hsz);
    ln_gelu_kernel<<<Bsz, 256>>>(pC1, g4, be4, pC2, pC1, Hsz);

    sgemm_nt<<<dim3((Hsz/2)/64, Bsz/64), 256>>>(pC1, w6, b6, pD1, Bsz, Hsz/2, Hsz);
    ln_gelu_kernel<<<Bsz, 256>>>(pD1, g5, be5, nullptr, pD1, Hsz/2);

    sgemm_nt<<<dim3((Hsz/4)/64, Bsz/64), 256>>>(pD1, w7, b7, pD2, Bsz, Hsz/4, Hsz/2);
    ln_gelu_kernel<<<Bsz, 256>>>(pD2, g6, be6, nullptr, pD2, Hsz/4);

    sgemm_nt<<<dim3(Lsz/64, Bsz/64), 256>>>(pD2, wout, bout, pBf, Bsz, Lsz, Hsz/4);
    sigmoid_kernel<<<(Bsz*Lsz)/256, 256>>>(pBf, pA);

    colstats_kernel<<<dim3(Lsz/256, CCH), 256>>>(pA);
    colcombine_kernel<<<Lsz/256, 256>>>();
    adjcons_kernel<<<1, 256>>>(fe);

    rowmask_kernel<<<Bsz, 256>>>(pA, ids, out, out + (size_t)Bsz * Ssz + 1);

    finalize_kernel<<<1, 256>>>(out);
}

// round 11
// speedup vs baseline: 1.9845x; 1.1144x over previous
#include <cuda_runtime.h>
#include <cuda_bf16.h>
#include <math.h>

// Problem constants
#define Bsz 4096
#define Ssz 1536
#define Lsz 2048
#define Hsz 1024
#define MINTOK 460                     // int(0.3*1536)
#define NEEDFIX_THRESH (Ssz - MINTOK)  // 1076

// ---------------- scratch (device globals; no allocations allowed) ----------
__device__ float g_A [(size_t)Bsz * Lsz];
__device__ float g_Bf[(size_t)Bsz * Lsz];
__device__ float g_C1[(size_t)Bsz * Hsz];
__device__ float g_C2[(size_t)Bsz * Hsz];
__device__ float g_C3[(size_t)Bsz * Hsz];
__device__ float g_D1[(size_t)Bsz * (Hsz/2)];
__device__ float g_D2[(size_t)Bsz * (Hsz/4)];

#define CCH 16
__device__ double g_p1[CCH * Lsz];
__device__ double g_p2[CCH * Lsz];
__device__ double g_p3[CCH * Lsz];
__device__ double g_S1[Lsz], g_S2[Lsz], g_S3[Lsz];
__device__ float  g_adj[Lsz];
__device__ float  g_rowEnt[Bsz], g_rowDiff[Bsz];
__device__ double g_cons[1];

// ---- f32x2 packed helpers (PTX-only; each half is an independent IEEE op) --
__device__ __forceinline__ unsigned long long pk2(float lo, float hi) {
    unsigned long long r;
    asm("mov.b64 %0, {%1, %2};" : "=l"(r) : "f"(lo), "f"(hi));
    return r;
}
__device__ __forceinline__ void upk2(unsigned long long v, float& lo, float& hi) {
    asm("mov.b64 {%0, %1}, %2;" : "=f"(lo), "=f"(hi) : "l"(v));
}
__device__ __forceinline__ unsigned long long fma2(unsigned long long a,
                                                   unsigned long long b,
                                                   unsigned long long c) {
    unsigned long long d;
    asm("fma.rn.f32x2 %0, %1, %2, %3;" : "=l"(d) : "l"(a), "l"(b), "l"(c));
    return d;
}

union F4U2 { float4 f; struct { unsigned long long lo, hi; } u; };

// ---------------- GEMM: C[M,N] = A[M,K] @ W[N,K]^T + bias[N] ----------------
// Numerics contract (frozen; outputs bitwise-identical to rounds 6-10): per
// output, fp32 FFMA over each ascending 64-k chunk; chunks folded ascending
// into a Kahan (ksum, kcmp) fp32 pair; (ksum+kcmp)+bias at the end. f32x2
// packs two M-adjacent outputs per instruction — identical IEEE arithmetic.
// Perf: 128x64 block tile, 8x4/thread (16 FFMA2 : 4 pk2 issue mix), 256
// threads, BK=16 double-buffered stages (small prefetch keeps regs <= ~126
// -> 2 CTAs/SM natural), Kahan fold every 4 stages (same 64-k chunks).
__global__ void __launch_bounds__(256)
sgemm_nt(const float* __restrict__ A, const float* __restrict__ W,
         const float* __restrict__ bias, float* __restrict__ C,
         int M, int N, int K)
{
    constexpr int BK = 16;
    __shared__ float As[2][BK][128];      // 16 KB (A reads are broadcast)
    __shared__ float Bs[2][BK][64 + 4];   // 8.7 KB
    const int tid = threadIdx.x;
    const int bm = blockIdx.y * 128;
    const int bn = blockIdx.x * 64;
    const int tr = (tid >> 4) << 3;     // 0..120 step 8 (C row offset)
    const int tc = (tid & 15) << 2;     // 0..60 step 4 (C col offset)

    // staging: A 128x16 -> 8 floats/thread; B 64x16 -> 4 floats/thread
    const int arow = tid & 127;
    const int ak   = (tid >> 7) << 3;   // 0 or 8
    const int brow = tid & 63;
    const int bk   = (tid >> 6) << 2;   // 0,4,8,12

    const float* Ap = A + (size_t)(bm + arow) * K + ak;
    const float* Wp = W + (size_t)(bn + brow) * K + bk;

    unsigned long long facc2[4][4];     // M-pairs (tr+2p, tr+2p+1) x 4 N
    float ksum[8][4], kcmp[8][4];
#pragma unroll
    for (int i = 0; i < 8; i++)
#pragma unroll
        for (int j = 0; j < 4; j++) { ksum[i][j] = 0.f; kcmp[i][j] = 0.f; }
#pragma unroll
    for (int p = 0; p < 4; p++)
#pragma unroll
        for (int j = 0; j < 4; j++) facc2[p][j] = 0ull;

    const int nch = K / BK;   // 16-k stages; Kahan fold every 4 stages (64 k)

    // prologue: stage chunk 0
    float4 aq0 = *(const float4*)(Ap);
    float4 aq1 = *(const float4*)(Ap + 4);
    float4 bq0 = *(const float4*)(Wp);
    As[0][ak + 0][arow] = aq0.x; As[0][ak + 1][arow] = aq0.y;
    As[0][ak + 2][arow] = aq0.z; As[0][ak + 3][arow] = aq0.w;
    As[0][ak + 4][arow] = aq1.x; As[0][ak + 5][arow] = aq1.y;
    As[0][ak + 6][arow] = aq1.z; As[0][ak + 7][arow] = aq1.w;
    Bs[0][bk + 0][brow] = bq0.x; Bs[0][bk + 1][brow] = bq0.y;
    Bs[0][bk + 2][brow] = bq0.z; Bs[0][bk + 3][brow] = bq0.w;
    __syncthreads();

    for (int c = 0; c < nch; c++) {
        const int buf = c & 1;
        const bool more = (c + 1 < nch);
        if (more) {
            const int k0 = (c + 1) * BK;
            aq0 = *(const float4*)(Ap + k0);
            aq1 = *(const float4*)(Ap + k0 + 4);
            bq0 = *(const float4*)(Wp + k0);
        }

#pragma unroll
        for (int k = 0; k < BK; k++) {
            F4U2 a0, a1;
            a0.f = *(const float4*)(&As[buf][k][tr]);
            a1.f = *(const float4*)(&As[buf][k][tr + 4]);
            const float4 bv = *(const float4*)(&Bs[buf][k][tc]);
            const unsigned long long bb0 = pk2(bv.x, bv.x);
            const unsigned long long bb1 = pk2(bv.y, bv.y);
            const unsigned long long bb2 = pk2(bv.z, bv.z);
            const unsigned long long bb3 = pk2(bv.w, bv.w);
            facc2[0][0] = fma2(a0.u.lo, bb0, facc2[0][0]);
            facc2[0][1] = fma2(a0.u.lo, bb1, facc2[0][1]);
            facc2[0][2] = fma2(a0.u.lo, bb2, facc2[0][2]);
            facc2[0][3] = fma2(a0.u.lo, bb3, facc2[0][3]);
            facc2[1][0] = fma2(a0.u.hi, bb0, facc2[1][0]);
            facc2[1][1] = fma2(a0.u.hi, bb1, facc2[1][1]);
            facc2[1][2] = fma2(a0.u.hi, bb2, facc2[1][2]);
            facc2[1][3] = fma2(a0.u.hi, bb3, facc2[1][3]);
            facc2[2][0] = fma2(a1.u.lo, bb0, facc2[2][0]);
            facc2[2][1] = fma2(a1.u.lo, bb1, facc2[2][1]);
            facc2[2][2] = fma2(a1.u.lo, bb2, facc2[2][2]);
            facc2[2][3] = fma2(a1.u.lo, bb3, facc2[2][3]);
            facc2[3][0] = fma2(a1.u.hi, bb0, facc2[3][0]);
            facc2[3][1] = fma2(a1.u.hi, bb1, facc2[3][1]);
            facc2[3][2] = fma2(a1.u.hi, bb2, facc2[3][2]);
            facc2[3][3] = fma2(a1.u.hi, bb3, facc2[3][3]);
        }

        if ((c & 3) == 3) {
            // Kahan fold of the completed 64-k chunk into (ksum, kcmp)
#pragma unroll
            for (int p = 0; p < 4; p++)
#pragma unroll
                for (int j = 0; j < 4; j++) {
                    float flo, fhi;
                    upk2(facc2[p][j], flo, fhi);
                    {
                        const int i = 2 * p;
                        const float t = __fadd_rn(ksum[i][j], flo);
                        const float e = __fadd_rn(__fsub_rn(ksum[i][j], t), flo);
                        kcmp[i][j] = __fadd_rn(kcmp[i][j], e);
                        ksum[i][j] = t;
                    }
                    {
                        const int i = 2 * p + 1;
                        const float t = __fadd_rn(ksum[i][j], fhi);
                        const float e = __fadd_rn(__fsub_rn(ksum[i][j], t), fhi);
                        kcmp[i][j] = __fadd_rn(kcmp[i][j], e);
                        ksum[i][j] = t;
                    }
                    facc2[p][j] = 0ull;
                }
        }

        if (more) {
            __syncthreads();
            const int nb = buf ^ 1;
            As[nb][ak + 0][arow] = aq0.x; As[nb][ak + 1][arow] = aq0.y;
            As[nb][ak + 2][arow] = aq0.z; As[nb][ak + 3][arow] = aq0.w;
            As[nb][ak + 4][arow] = aq1.x; As[nb][ak + 5][arow] = aq1.y;
            As[nb][ak + 6][arow] = aq1.z; As[nb][ak + 7][arow] = aq1.w;
            Bs[nb][bk + 0][brow] = bq0.x; Bs[nb][bk + 1][brow] = bq0.y;
            Bs[nb][bk + 2][brow] = bq0.z; Bs[nb][bk + 3][brow] = bq0.w;
            __syncthreads();
        }
    }

    float bj[4];
#pragma unroll
    for (int j = 0; j < 4; j++) bj[j] = bias[bn + tc + j];
#pragma unroll
    for (int i = 0; i < 8; i++) {
        float* Cp = C + (size_t)(bm + tr + i) * N + bn + tc;
        float4 v;
        v.x = __fadd_rn(__fadd_rn(ksum[i][0], kcmp[i][0]), bj[0]);
        v.y = __fadd_rn(__fadd_rn(ksum[i][1], kcmp[i][1]), bj[1]);
        v.z = __fadd_rn(__fadd_rn(ksum[i][2], kcmp[i][2]), bj[2]);
        v.w = __fadd_rn(__fadd_rn(ksum[i][3], kcmp[i][3]), bj[3]);
        *(float4*)Cp = v;
    }
}

// ---------------- LN of padded int input -> X0 (double-precise stats) -------
__global__ void ln_input_kernel(const int* __restrict__ ids,
                                const float* __restrict__ gam,
                                const float* __restrict__ bet,
                                float* __restrict__ out)
{
    __shared__ float s[Lsz];
    __shared__ double red[256];
    const int r = blockIdx.x, tid = threadIdx.x;
    for (int j = tid; j < Lsz; j += 256)
        s[j] = (j < Ssz) ? (float)ids[(size_t)r * Ssz + j] : 0.f;
    __syncthreads();
    double p = 0.0;
    for (int j = tid; j < Lsz; j += 256) p += (double)s[j];
    red[tid] = p; __syncthreads();
    for (int o = 128; o > 0; o >>= 1) { if (tid < o) red[tid] += red[tid + o]; __syncthreads(); }
    const double mean = red[0] / (double)Lsz;
    const float  mf   = (float)mean;
    __syncthreads();
    double v = 0.0;
    for (int j = tid; j < Lsz; j += 256) { double d = (double)s[j] - mean; v += d * d; }
    red[tid] = v; __syncthreads();
    for (int o = 128; o > 0; o >>= 1) { if (tid < o) red[tid] += red[tid + o]; __syncthreads(); }
    const float vf  = (float)(red[0] / (double)Lsz);
    const float arg = __fadd_rn(vf, 1e-5f);
    const float rs  = (float)(1.0 / sqrt((double)arg));
    for (int j = tid; j < Lsz; j += 256) {
        float t = __fmul_rn(__fmul_rn(__fsub_rn(s[j], mf), rs), gam[j]);
        out[(size_t)r * Lsz + j] = __fadd_rn(t, bet[j]);
    }
}

// ---------------- LN + exact GELU (+ optional residual), per row ------------
__global__ void ln_gelu_kernel(const float* __restrict__ in,
                               const float* __restrict__ gam,
                               const float* __restrict__ bet,
                               const float* __restrict__ res,
                               float* __restrict__ out, int n)
{
    __shared__ float s[Lsz];
    __shared__ double red[256];
    const int r = blockIdx.x, tid = threadIdx.x;
    for (int j = tid; j < n; j += 256) s[j] = in[(size_t)r * n + j];
    __syncthreads();
    double p = 0.0;
    for (int j = tid; j < n; j += 256) p += (double)s[j];
    red[tid] = p; __syncthreads();
    for (int o = 128; o > 0; o >>= 1) { if (tid < o) red[tid] += red[tid + o]; __syncthreads(); }
    const double mean = red[0] / (double)n;
    const float  mf   = (float)mean;
    __syncthreads();
    double v = 0.0;
    for (int j = tid; j < n; j += 256) { double d = (double)s[j] - mean; v += d * d; }
    red[tid] = v; __syncthreads();
    for (int o = 128; o > 0; o >>= 1) { if (tid < o) red[tid] += red[tid + o]; __syncthreads(); }
    const float vf  = (float)(red[0] / (double)n);
    const float arg = __fadd_rn(vf, 1e-5f);
    const float rs  = (float)(1.0 / sqrt((double)arg));
    for (int j = tid; j < n; j += 256) {
        float x = __fadd_rn(__fmul_rn(__fmul_rn(__fsub_rn(s[j], mf), rs), gam[j]), bet[j]);
        float u = __fmul_rn(x, 0.70710678118654752f);
        float e = erff(u);
        float ge = __fmul_rn(__fmul_rn(x, __fadd_rn(e, 1.f)), 0.5f);
        float o = res ? __fadd_rn(ge, res[(size_t)r * n + j]) : ge;
        out[(size_t)r * n + j] = o;
    }
}

// ---------------- mu -> z = sigmoid(clip(mu,-5,5)), exact -------------------
__global__ void sigmoid_kernel(const float* __restrict__ mu, float* __restrict__ z)
{
    size_t i = (size_t)blockIdx.x * 256 + threadIdx.x;
    if (i < (size_t)Bsz * Lsz) {
        float m = mu[i];
        m = fminf(5.f, fmaxf(-5.f, m));
        z[i] = (float)(1.0 / (1.0 + exp(-(double)m)));
    }
}

// ---------------- column stats ----------------------------------------------
__global__ void colstats_kernel(const float* __restrict__ Z)
{
    const int j  = blockIdx.x * 256 + threadIdx.x;
    const int ch = blockIdx.y;
    const int r0 = ch * (Bsz / CCH);
    const bool hasN = (j < Lsz - 1);
    double s1 = 0, s2 = 0, s3 = 0;
    for (int r = r0; r < r0 + (Bsz / CCH); ++r) {
        float z  = Z[(size_t)r * Lsz + j];
        float zn = hasN ? Z[(size_t)r * Lsz + j + 1] : 0.f;
        s1 += (double)z;
        s2 += (double)z * (double)z;
        s3 += (double)z * (double)zn;
    }
    g_p1[ch * Lsz + j] = s1;
    g_p2[ch * Lsz + j] = s2;
    g_p3[ch * Lsz + j] = s3;
}

__global__ void colcombine_kernel()
{
    const int j = blockIdx.x * 256 + threadIdx.x;
    double s1 = 0, s2 = 0, s3 = 0;
    for (int c = 0; c < CCH; c++) {
        s1 += g_p1[c * Lsz + j];
        s2 += g_p2[c * Lsz + j];
        s3 += g_p3[c * Lsz + j];
    }
    g_S1[j] = s1; g_S2[j] = s2; g_S3[j] = s3;
}

// ---------------- adj (corr>0.5) + consistency term -------------------------
__global__ void adjcons_kernel(const float* __restrict__ fe)
{
    __shared__ double red[256];
    const int tid = threadIdx.x;
    double cons = 0.0;
    for (int j = tid; j < Lsz; j += 256) {
        double m = g_S1[j] / (double)Bsz;
        cons += fabs(m - (double)fe[j]);
        if (j < Lsz - 1) {
            double cov = g_S3[j] - g_S1[j] * g_S1[j + 1] / (double)Bsz;
            double v1  = g_S2[j]     - g_S1[j]     * g_S1[j]     / (double)Bsz;
            double v2  = g_S2[j + 1] - g_S1[j + 1] * g_S1[j + 1] / (double)Bsz;
            double den = v1 * v2;
            float a = 0.f;
            if (den > 0.0 && cov / sqrt(den) > 0.5) a = 1.f;
            g_adj[j] = a;
        }
    }
    red[tid] = cons; __syncthreads();
    for (int o = 128; o > 0; o >>= 1) { if (tid < o) red[tid] += red[tid + o]; __syncthreads(); }
    if (tid == 0) g_cons[0] = red[0];
}

// ---------------- per-row mask / top-k / outputs -----------------------------
__global__ void __launch_bounds__(256)
rowmask_kernel(const float* __restrict__ Z, const int* __restrict__ ids,
               float* __restrict__ outG, float* __restrict__ outZ)
{
    __shared__ float zs[Lsz];
    __shared__ float redf[256];
    __shared__ int   redi[256];
    __shared__ unsigned int hist[256];
    __shared__ unsigned int sh_prefix;
    __shared__ int sh_k;
    __shared__ int wsum[8];

    const int r = blockIdx.x, tid = threadIdx.x;
    for (int j = tid; j < Lsz; j += 256) zs[j] = Z[(size_t)r * Lsz + j];
    __syncthreads();

    float ent = 0.f, dif = 0.f;
    int cnt = 0;
    for (int j = tid; j < Lsz; j += 256) {
        float p = zs[j];
        ent += -(p * logf(__fadd_rn(p, 1e-7f)) +
                 (1.f - p) * logf(__fadd_rn(__fsub_rn(1.f, p), 1e-7f)));
        if (j < Lsz - 1) dif += fabsf(__fsub_rn(zs[j + 1], zs[j])) * g_adj[j];
        if (j < Ssz) {
            int tok = ids[(size_t)r * Ssz + j];
            if (p < 0.5f && tok != 0) cnt++;
        }
    }
    redf[tid] = ent; __syncthreads();
    for (int o = 128; o > 0; o >>= 1) { if (tid < o) redf[tid] += redf[tid + o]; __syncthreads(); }
    if (tid == 0) g_rowEnt[r] = redf[0];
    __syncthreads();
    redf[tid] = dif; __syncthreads();
    for (int o = 128; o > 0; o >>= 1) { if (tid < o) redf[tid] += redf[tid + o]; __syncthreads(); }
    if (tid == 0) g_rowDiff[r] = redf[0];
    __syncthreads();
    redi[tid] = cnt; __syncthreads();
    for (int o = 128; o > 0; o >>= 1) { if (tid < o) redi[tid] += redi[tid + o]; __syncthreads(); }
    const int total = redi[0];
    __syncthreads();
    const bool needfix = total > NEEDFIX_THRESH;

    unsigned int tsel = 0;
    int nEqKeep = 0;
    if (needfix) {
        unsigned int prefix = 0, highmask = 0;
        int k = MINTOK;
        for (int pass = 0; pass < 4; pass++) {
            const int shift = 24 - 8 * pass;
            hist[tid] = 0;
            __syncthreads();
            for (int j = tid; j < Ssz; j += 256) {
                unsigned int key = __float_as_uint(zs[j]);
                if ((key & highmask) == prefix)
                    atomicAdd(&hist[(key >> shift) & 0xFFu], 1u);
            }
            __syncthreads();
            if (tid == 0) {
                int cum = 0, b = 255;
                for (; b >= 0; --b) { cum += (int)hist[b]; if (cum >= k) break; }
                sh_k = k - (cum - (int)hist[b]);
                sh_prefix = prefix | ((unsigned int)b << shift);
            }
            __syncthreads();
            prefix = sh_prefix;
            k = sh_k;
            highmask |= 0xFFu << shift;
            __syncthreads();
        }
        tsel = prefix;
        int cg = 0;
        for (int j = tid; j < Ssz; j += 256)
            if (__float_as_uint(zs[j]) > tsel) cg++;
        redi[tid] = cg; __syncthreads();
        for (int o = 128; o > 0; o >>= 1) { if (tid < o) redi[tid] += redi[tid + o]; __syncthreads(); }
        nEqKeep = MINTOK - redi[0];
        __syncthreads();
    }

    int runEq = 0;
    for (int base = 0; base < Ssz; base += 256) {
        const int j = base + tid;
        const float zv = zs[j];
        const int tok = ids[(size_t)r * Ssz + j];
        bool m = (zv < 0.5f) && (tok != 0);
        if (needfix) {
            const unsigned int key = __float_as_uint(zv);
            const int eq = (key == tsel) ? 1 : 0;
            const unsigned int bal = __ballot_sync(0xffffffffu, eq);
            const int lane = tid & 31, w = tid >> 5;
            const int wexcl = __popc(bal & ((1u << lane) - 1u));
            if (lane == 31) wsum[w] = __popc(bal);
            __syncthreads();
            int woff = 0;
            for (int i = 0; i < w; i++) woff += wsum[i];
            const int excl = woff + wexcl;
            const bool keep = (key > tsel) || (eq && (runEq + excl) < nEqKeep);
            if (keep) m = false;
            __syncthreads();
            if (tid == 0) { int t = 0; for (int i = 0; i < 8; i++) t += wsum[i]; redi[0] = t; }
            __syncthreads();
            runEq += redi[0];
        }
        if (j == 0) m = false;
        outG[(size_t)r * Ssz + j] = m ? 0.f : (float)tok;
        outZ[(size_t)r * Ssz + j] = zv;
    }
}

// ---------------- final loss scalar -----------------------------------------
__global__ void finalize_kernel(float* __restrict__ out)
{
    __shared__ double red[256];
    const int tid = threadIdx.x;
    double e = 0, d = 0;
    for (int r = tid; r < Bsz; r += 256) {
        e += (double)g_rowEnt[r];
        d += (double)g_rowDiff[r];
    }
    red[tid] = e; __syncthreads();
    for (int o = 128; o > 0; o >>= 1) { if (tid < o) red[tid] += red[tid + o]; __syncthreads(); }
    const double entSum = red[0];
    __syncthreads();
    red[tid] = d; __syncthreads();
    for (int o = 128; o > 0; o >>= 1) { if (tid < o) red[tid] += red[tid + o]; __syncthreads(); }
    const double difSum = red[0];
    if (tid == 0) {
        double R1 = -0.001 * entSum / ((double)Bsz * (double)Lsz);
        double R2 =  0.001 * difSum / ((double)Bsz * (double)(Lsz - 1));
        double cons = 0.001 * g_cons[0] / (double)Lsz;
        out[(size_t)Bsz * Ssz] = (float)(R1 + R2 + cons);
    }
}

// ---------------- launch ------------------------------------------------------
extern "C" void kernel_launch(void* const* d_in, const int* in_sizes, int n_in,
                              void* d_out, int out_size)
{
    const float* in_g  = (const float*)d_in[0];
    const float* in_b  = (const float*)d_in[1];
    const float* wv    = (const float*)d_in[2];
    const float* bv    = (const float*)d_in[3];
    const float* wo    = (const float*)d_in[4];
    const float* bo    = (const float*)d_in[5];
    const float* w2    = (const float*)d_in[6];
    const float* b2    = (const float*)d_in[7];
    const float* g1    = (const float*)d_in[8];
    const float* be1   = (const float*)d_in[9];
    const float* w4    = (const float*)d_in[10];
    const float* b4    = (const float*)d_in[11];
    const float* g3    = (const float*)d_in[12];
    const float* be3   = (const float*)d_in[13];
    const float* w5    = (const float*)d_in[14];
    const float* b5    = (const float*)d_in[15];
    const float* g4    = (const float*)d_in[16];
    const float* be4   = (const float*)d_in[17];
    const float* w6    = (const float*)d_in[18];
    const float* b6    = (const float*)d_in[19];
    const float* g5    = (const float*)d_in[20];
    const float* be5   = (const float*)d_in[21];
    const float* w7    = (const float*)d_in[22];
    const float* b7    = (const float*)d_in[23];
    const float* g6    = (const float*)d_in[24];
    const float* be6   = (const float*)d_in[25];
    const float* wout  = (const float*)d_in[26];
    const float* bout  = (const float*)d_in[27];
    const float* fe    = (const float*)d_in[28];
    const int*   ids   = (const int*)d_in[29];
    float* out = (float*)d_out;

    float *pA, *pBf, *pC1, *pC2, *pC3, *pD1, *pD2;
    cudaGetSymbolAddress((void**)&pA,  g_A);
    cudaGetSymbolAddress((void**)&pBf, g_Bf);
    cudaGetSymbolAddress((void**)&pC1, g_C1);
    cudaGetSymbolAddress((void**)&pC2, g_C2);
    cudaGetSymbolAddress((void**)&pC3, g_C3);
    cudaGetSymbolAddress((void**)&pD1, g_D1);
    cudaGetSymbolAddress((void**)&pD2, g_D2);

    ln_input_kernel<<<Bsz, 256>>>(ids, in_g, in_b, pA);

    sgemm_nt<<<dim3(Lsz/64, Bsz/128), 256>>>(pA,  wv, bv, pBf, Bsz, Lsz, Lsz);
    sgemm_nt<<<dim3(Lsz/64, Bsz/128), 256>>>(pBf, wo, bo, pA,  Bsz, Lsz, Lsz);

    sgemm_nt<<<dim3(Hsz/64, Bsz/128), 256>>>(pA, w2, b2, pC1, Bsz, Hsz, Lsz);
    ln_gelu_kernel<<<Bsz, 256>>>(pC1, g1, be1, pC1, pC2, Hsz);

    sgemm_nt<<<dim3(Hsz/64, Bsz/128), 256>>>(pC2, w4, b4, pC3, Bsz, Hsz, Hsz);
    ln_gelu_kernel<<<Bsz, 256>>>(pC3, g3, be3, nullptr, pC3, Hsz);

    sgemm_nt<<<dim3(Hsz/64, Bsz/128), 256>>>(pC3, w5, b5, pC1, Bsz, Hsz, Hsz);
    ln_gelu_kernel<<<Bsz, 256>>>(pC1, g4, be4, pC2, pC1, Hsz);

    sgemm_nt<<<dim3((Hsz/2)/64, Bsz/128), 256>>>(pC1, w6, b6, pD1, Bsz, Hsz/2, Hsz);
    ln_gelu_kernel<<<Bsz, 256>>>(pD1, g5, be5, nullptr, pD1, Hsz/2);

    sgemm_nt<<<dim3((Hsz/4)/64, Bsz/128), 256>>>(pD1, w7, b7, pD2, Bsz, Hsz/4, Hsz/2);
    ln_gelu_kernel<<<Bsz, 256>>>(pD2, g6, be6, nullptr, pD2, Hsz/4);

    sgemm_nt<<<dim3(Lsz/64, Bsz/128), 256>>>(pD2, wout, bout, pBf, Bsz, Lsz, Hsz/4);
    sigmoid_kernel<<<(Bsz*Lsz)/256, 256>>>(pBf, pA);

    colstats_kernel<<<dim3(Lsz/256, CCH), 256>>>(pA);
    colcombine_kernel<<<Lsz/256, 256>>>();
    adjcons_kernel<<<1, 256>>>(fe);

    rowmask_kernel<<<Bsz, 256>>>(pA, ids, out, out + (size_t)Bsz * Ssz + 1);

    finalize_kernel<<<1, 256>>>(out);
}

// round 12
// speedup vs baseline: 2.1431x; 1.0799x over previous
#include <cuda_runtime.h>
#include <cuda_bf16.h>
#include <math.h>

// Problem constants
#define Bsz 4096
#define Ssz 1536
#define Lsz 2048
#define Hsz 1024
#define MINTOK 460                     // int(0.3*1536)
#define NEEDFIX_THRESH (Ssz - MINTOK)  // 1076

// ---------------- scratch (device globals; no allocations allowed) ----------
__device__ float g_A [(size_t)Bsz * Lsz];
__device__ float g_Bf[(size_t)Bsz * Lsz];
__device__ float g_C1[(size_t)Bsz * Hsz];
__device__ float g_C2[(size_t)Bsz * Hsz];
__device__ float g_C3[(size_t)Bsz * Hsz];
__device__ float g_D1[(size_t)Bsz * (Hsz/2)];
__device__ float g_D2[(size_t)Bsz * (Hsz/4)];

#define CCH 64
__device__ double g_p1[CCH * Lsz];
__device__ double g_p2[CCH * Lsz];
__device__ double g_p3[CCH * Lsz];
__device__ double g_S1[Lsz], g_S2[Lsz], g_S3[Lsz];
__device__ float  g_adj[Lsz];
__device__ float  g_rowEnt[Bsz], g_rowDiff[Bsz];
__device__ double g_cons[1];

// ---- f32x2 packed helpers (PTX-only; each half is an independent IEEE op) --
__device__ __forceinline__ unsigned long long pk2(float lo, float hi) {
    unsigned long long r;
    asm("mov.b64 %0, {%1, %2};" : "=l"(r) : "f"(lo), "f"(hi));
    return r;
}
__device__ __forceinline__ void upk2(unsigned long long v, float& lo, float& hi) {
    asm("mov.b64 {%0, %1}, %2;" : "=f"(lo), "=f"(hi) : "l"(v));
}
__device__ __forceinline__ unsigned long long fma2(unsigned long long a,
                                                   unsigned long long b,
                                                   unsigned long long c) {
    unsigned long long d;
    asm("fma.rn.f32x2 %0, %1, %2, %3;" : "=l"(d) : "l"(a), "l"(b), "l"(c));
    return d;
}

union F4U2 { float4 f; struct { unsigned long long lo, hi; } u; };

__device__ __forceinline__ double warp_rsum_d(double x) {
#pragma unroll
    for (int o = 16; o > 0; o >>= 1)
        x += __shfl_down_sync(0xffffffffu, x, o);
    return x;
}

// ---------------- GEMM: C[M,N] = A[M,K] @ W[N,K]^T + bias[N] ----------------
// Numerics contract (frozen; outputs bitwise-identical to rounds 6-11): per
// output, fp32 FFMA over each ascending 64-k chunk; chunks folded ascending
// into a Kahan (ksum, kcmp) fp32 pair; (ksum+kcmp)+bias at the end. f32x2
// packs two M-adjacent outputs per instruction — identical IEEE arithmetic.
// Perf: 128x64 block tile, 8x4/thread, 256 threads, BK=16 double-buffered
// smem stages + gmem register prefetch + SOFTWARE-PIPELINED inner k-loop
// (smem operands for k+1 loaded during k's FMAs -> LDS latency hidden).
__global__ void __launch_bounds__(256)
sgemm_nt(const float* __restrict__ A, const float* __restrict__ W,
         const float* __restrict__ bias, float* __restrict__ C,
         int M, int N, int K)
{
    constexpr int BK = 16;
    __shared__ float As[2][BK][128];
    __shared__ float Bs[2][BK][64 + 4];
    const int tid = threadIdx.x;
    const int bm = blockIdx.y * 128;
    const int bn = blockIdx.x * 64;
    const int tr = (tid >> 4) << 3;     // 0..120 step 8
    const int tc = (tid & 15) << 2;     // 0..60 step 4

    const int arow = tid & 127;
    const int ak   = (tid >> 7) << 3;   // 0 or 8
    const int brow = tid & 63;
    const int bk   = (tid >> 6) << 2;   // 0,4,8,12

    const float* Ap = A + (size_t)(bm + arow) * K + ak;
    const float* Wp = W + (size_t)(bn + brow) * K + bk;

    unsigned long long facc2[4][4];
    float ksum[8][4], kcmp[8][4];
#pragma unroll
    for (int i = 0; i < 8; i++)
#pragma unroll
        for (int j = 0; j < 4; j++) { ksum[i][j] = 0.f; kcmp[i][j] = 0.f; }
#pragma unroll
    for (int p = 0; p < 4; p++)
#pragma unroll
        for (int j = 0; j < 4; j++) facc2[p][j] = 0ull;

    const int nch = K / BK;   // 16-k stages; Kahan fold every 4 stages (64 k)

    float4 aq0 = *(const float4*)(Ap);
    float4 aq1 = *(const float4*)(Ap + 4);
    float4 bq0 = *(const float4*)(Wp);
    As[0][ak + 0][arow] = aq0.x; As[0][ak + 1][arow] = aq0.y;
    As[0][ak + 2][arow] = aq0.z; As[0][ak + 3][arow] = aq0.w;
    As[0][ak + 4][arow] = aq1.x; As[0][ak + 5][arow] = aq1.y;
    As[0][ak + 6][arow] = aq1.z; As[0][ak + 7][arow] = aq1.w;
    Bs[0][bk + 0][brow] = bq0.x; Bs[0][bk + 1][brow] = bq0.y;
    Bs[0][bk + 2][brow] = bq0.z; Bs[0][bk + 3][brow] = bq0.w;
    __syncthreads();

    for (int c = 0; c < nch; c++) {
        const int buf = c & 1;
        const bool more = (c + 1 < nch);
        if (more) {
            const int k0 = (c + 1) * BK;
            aq0 = *(const float4*)(Ap + k0);
            aq1 = *(const float4*)(Ap + k0 + 4);
            bq0 = *(const float4*)(Wp + k0);
        }

        // software-pipelined inner loop: operands for k+1 load during k's FMAs
        F4U2 a0c, a1c; float4 bvc;
        a0c.f = *(const float4*)(&As[buf][0][tr]);
        a1c.f = *(const float4*)(&As[buf][0][tr + 4]);
        bvc   = *(const float4*)(&Bs[buf][0][tc]);
#pragma unroll
        for (int k = 0; k < BK; k++) {
            F4U2 a0n, a1n; float4 bvn;
            if (k + 1 < BK) {
                a0n.f = *(const float4*)(&As[buf][k + 1][tr]);
                a1n.f = *(const float4*)(&As[buf][k + 1][tr + 4]);
                bvn   = *(const float4*)(&Bs[buf][k + 1][tc]);
            }
            const unsigned long long bb0 = pk2(bvc.x, bvc.x);
            const unsigned long long bb1 = pk2(bvc.y, bvc.y);
            const unsigned long long bb2 = pk2(bvc.z, bvc.z);
            const unsigned long long bb3 = pk2(bvc.w, bvc.w);
            facc2[0][0] = fma2(a0c.u.lo, bb0, facc2[0][0]);
            facc2[0][1] = fma2(a0c.u.lo, bb1, facc2[0][1]);
            facc2[0][2] = fma2(a0c.u.lo, bb2, facc2[0][2]);
            facc2[0][3] = fma2(a0c.u.lo, bb3, facc2[0][3]);
            facc2[1][0] = fma2(a0c.u.hi, bb0, facc2[1][0]);
            facc2[1][1] = fma2(a0c.u.hi, bb1, facc2[1][1]);
            facc2[1][2] = fma2(a0c.u.hi, bb2, facc2[1][2]);
            facc2[1][3] = fma2(a0c.u.hi, bb3, facc2[1][3]);
            facc2[2][0] = fma2(a1c.u.lo, bb0, facc2[2][0]);
            facc2[2][1] = fma2(a1c.u.lo, bb1, facc2[2][1]);
            facc2[2][2] = fma2(a1c.u.lo, bb2, facc2[2][2]);
            facc2[2][3] = fma2(a1c.u.lo, bb3, facc2[2][3]);
            facc2[3][0] = fma2(a1c.u.hi, bb0, facc2[3][0]);
            facc2[3][1] = fma2(a1c.u.hi, bb1, facc2[3][1]);
            facc2[3][2] = fma2(a1c.u.hi, bb2, facc2[3][2]);
            facc2[3][3] = fma2(a1c.u.hi, bb3, facc2[3][3]);
            if (k + 1 < BK) { a0c = a0n; a1c = a1n; bvc = bvn; }
        }

        if ((c & 3) == 3) {
#pragma unroll
            for (int p = 0; p < 4; p++)
#pragma unroll
                for (int j = 0; j < 4; j++) {
                    float flo, fhi;
                    upk2(facc2[p][j], flo, fhi);
                    {
                        const int i = 2 * p;
                        const float t = __fadd_rn(ksum[i][j], flo);
                        const float e = __fadd_rn(__fsub_rn(ksum[i][j], t), flo);
                        kcmp[i][j] = __fadd_rn(kcmp[i][j], e);
                        ksum[i][j] = t;
                    }
                    {
                        const int i = 2 * p + 1;
                        const float t = __fadd_rn(ksum[i][j], fhi);
                        const float e = __fadd_rn(__fsub_rn(ksum[i][j], t), fhi);
                        kcmp[i][j] = __fadd_rn(kcmp[i][j], e);
                        ksum[i][j] = t;
                    }
                    facc2[p][j] = 0ull;
                }
        }

        if (more) {
            __syncthreads();
            const int nb = buf ^ 1;
            As[nb][ak + 0][arow] = aq0.x; As[nb][ak + 1][arow] = aq0.y;
            As[nb][ak + 2][arow] = aq0.z; As[nb][ak + 3][arow] = aq0.w;
            As[nb][ak + 4][arow] = aq1.x; As[nb][ak + 5][arow] = aq1.y;
            As[nb][ak + 6][arow] = aq1.z; As[nb][ak + 7][arow] = aq1.w;
            Bs[nb][bk + 0][brow] = bq0.x; Bs[nb][bk + 1][brow] = bq0.y;
            Bs[nb][bk + 2][brow] = bq0.z; Bs[nb][bk + 3][brow] = bq0.w;
            __syncthreads();
        }
    }

    float bj[4];
#pragma unroll
    for (int j = 0; j < 4; j++) bj[j] = bias[bn + tc + j];
#pragma unroll
    for (int i = 0; i < 8; i++) {
        float* Cp = C + (size_t)(bm + tr + i) * N + bn + tc;
        float4 v;
        v.x = __fadd_rn(__fadd_rn(ksum[i][0], kcmp[i][0]), bj[0]);
        v.y = __fadd_rn(__fadd_rn(ksum[i][1], kcmp[i][1]), bj[1]);
        v.z = __fadd_rn(__fadd_rn(ksum[i][2], kcmp[i][2]), bj[2]);
        v.w = __fadd_rn(__fadd_rn(ksum[i][3], kcmp[i][3]), bj[3]);
        *(float4*)Cp = v;
    }
}

// ---------------- LN of padded int input -> X0 ------------------------------
// Register-resident, warp-shuffle double reductions (stat rounding changes at
// ~1e-16 only). Elementwise fp32 op sequence unchanged.
__global__ void __launch_bounds__(256)
ln_input_kernel(const int* __restrict__ ids,
                const float* __restrict__ gam,
                const float* __restrict__ bet,
                float* __restrict__ out)
{
    constexpr int NE = 8;   // 2048 / 256
    __shared__ double sw[8];
    __shared__ double sbc;
    const int r = blockIdx.x, tid = threadIdx.x;
    float v[NE];
#pragma unroll
    for (int i = 0; i < NE; i++) {
        const int j = tid + (i << 8);
        v[i] = (j < Ssz) ? (float)ids[(size_t)r * Ssz + j] : 0.f;
    }
    double p = 0.0;
#pragma unroll
    for (int i = 0; i < NE; i++) p += (double)v[i];
    double ws = warp_rsum_d(p);
    if ((tid & 31) == 0) sw[tid >> 5] = ws;
    __syncthreads();
    if (tid == 0) { double t = 0; for (int i = 0; i < 8; i++) t += sw[i]; sbc = t; }
    __syncthreads();
    const double mean = sbc / (double)Lsz;
    const float  mf   = (float)mean;
    double vv = 0.0;
#pragma unroll
    for (int i = 0; i < NE; i++) { double d = (double)v[i] - mean; vv += d * d; }
    ws = warp_rsum_d(vv);
    __syncthreads();
    if ((tid & 31) == 0) sw[tid >> 5] = ws;
    __syncthreads();
    if (tid == 0) { double t = 0; for (int i = 0; i < 8; i++) t += sw[i]; sbc = t; }
    __syncthreads();
    const float vf  = (float)(sbc / (double)Lsz);
    const float arg = __fadd_rn(vf, 1e-5f);
    const float rs  = (float)(1.0 / sqrt((double)arg));
#pragma unroll
    for (int i = 0; i < NE; i++) {
        const int j = tid + (i << 8);
        float t = __fmul_rn(__fmul_rn(__fsub_rn(v[i], mf), rs), gam[j]);
        out[(size_t)r * Lsz + j] = __fadd_rn(t, bet[j]);
    }
}

// ---------------- LN + exact GELU (+ optional residual), per row ------------
template<int NE>
__global__ void __launch_bounds__(256)
ln_gelu_kernel(const float* __restrict__ in,
               const float* __restrict__ gam,
               const float* __restrict__ bet,
               const float* __restrict__ res,
               float* __restrict__ out)
{
    constexpr int n = NE * 256;
    __shared__ double sw[8];
    __shared__ double sbc;
    const int r = blockIdx.x, tid = threadIdx.x;
    float v[NE];
#pragma unroll
    for (int i = 0; i < NE; i++) v[i] = in[(size_t)r * n + tid + (i << 8)];
    double p = 0.0;
#pragma unroll
    for (int i = 0; i < NE; i++) p += (double)v[i];
    double ws = warp_rsum_d(p);
    if ((tid & 31) == 0) sw[tid >> 5] = ws;
    __syncthreads();
    if (tid == 0) { double t = 0; for (int i = 0; i < 8; i++) t += sw[i]; sbc = t; }
    __syncthreads();
    const double mean = sbc / (double)n;
    const float  mf   = (float)mean;
    double vv = 0.0;
#pragma unroll
    for (int i = 0; i < NE; i++) { double d = (double)v[i] - mean; vv += d * d; }
    ws = warp_rsum_d(vv);
    __syncthreads();
    if ((tid & 31) == 0) sw[tid >> 5] = ws;
    __syncthreads();
    if (tid == 0) { double t = 0; for (int i = 0; i < 8; i++) t += sw[i]; sbc = t; }
    __syncthreads();
    const float vf  = (float)(sbc / (double)n);
    const float arg = __fadd_rn(vf, 1e-5f);
    const float rs  = (float)(1.0 / sqrt((double)arg));
#pragma unroll
    for (int i = 0; i < NE; i++) {
        const int j = tid + (i << 8);
        float x = __fadd_rn(__fmul_rn(__fmul_rn(__fsub_rn(v[i], mf), rs), gam[j]), bet[j]);
        float u = __fmul_rn(x, 0.70710678118654752f);
        float e = erff(u);
        float ge = __fmul_rn(__fmul_rn(x, __fadd_rn(e, 1.f)), 0.5f);
        float o = res ? __fadd_rn(ge, res[(size_t)r * n + j]) : ge;
        out[(size_t)r * n + j] = o;
    }
}

// ---------------- mu -> z = sigmoid(clip(mu,-5,5)), exact -------------------
__global__ void sigmoid_kernel(const float* __restrict__ mu, float* __restrict__ z)
{
    size_t i = (size_t)blockIdx.x * 256 + threadIdx.x;
    if (i < (size_t)Bsz * Lsz) {
        float m = mu[i];
        m = fminf(5.f, fmaxf(-5.f, m));
        z[i] = (float)(1.0 / (1.0 + exp(-(double)m)));
    }
}

// ---------------- column stats ----------------------------------------------
__global__ void colstats_kernel(const float* __restrict__ Z)
{
    const int j  = blockIdx.x * 256 + threadIdx.x;
    const int ch = blockIdx.y;
    const int r0 = ch * (Bsz / CCH);
    const bool hasN = (j < Lsz - 1);
    double s1 = 0, s2 = 0, s3 = 0;
    for (int r = r0; r < r0 + (Bsz / CCH); ++r) {
        float z  = Z[(size_t)r * Lsz + j];
        float zn = hasN ? Z[(size_t)r * Lsz + j + 1] : 0.f;
        s1 += (double)z;
        s2 += (double)z * (double)z;
        s3 += (double)z * (double)zn;
    }
    g_p1[ch * Lsz + j] = s1;
    g_p2[ch * Lsz + j] = s2;
    g_p3[ch * Lsz + j] = s3;
}

__global__ void colcombine_kernel()
{
    const int j = blockIdx.x * 256 + threadIdx.x;
    double s1 = 0, s2 = 0, s3 = 0;
    for (int c = 0; c < CCH; c++) {
        s1 += g_p1[c * Lsz + j];
        s2 += g_p2[c * Lsz + j];
        s3 += g_p3[c * Lsz + j];
    }
    g_S1[j] = s1; g_S2[j] = s2; g_S3[j] = s3;
}

// ---------------- adj (corr>0.5) + consistency term -------------------------
__global__ void adjcons_kernel(const float* __restrict__ fe)
{
    __shared__ double red[256];
    const int tid = threadIdx.x;
    double cons = 0.0;
    for (int j = tid; j < Lsz; j += 256) {
        double m = g_S1[j] / (double)Bsz;
        cons += fabs(m - (double)fe[j]);
        if (j < Lsz - 1) {
            double cov = g_S3[j] - g_S1[j] * g_S1[j + 1] / (double)Bsz;
            double v1  = g_S2[j]     - g_S1[j]     * g_S1[j]     / (double)Bsz;
            double v2  = g_S2[j + 1] - g_S1[j + 1] * g_S1[j + 1] / (double)Bsz;
            double den = v1 * v2;
            float a = 0.f;
            if (den > 0.0 && cov / sqrt(den) > 0.5) a = 1.f;
            g_adj[j] = a;
        }
    }
    red[tid] = cons; __syncthreads();
    for (int o = 128; o > 0; o >>= 1) { if (tid < o) red[tid] += red[tid + o]; __syncthreads(); }
    if (tid == 0) g_cons[0] = red[0];
}

// ---------------- per-row mask / top-k / outputs -----------------------------
// Phase 1: warp-shuffle reductions (ent/dif feed only the loss scalar; cnt is
// integer-exact). Phase 2: contiguous 6-elements/thread ownership with one
// block scan for tie ranks (identical rank semantics, ~3 barriers vs ~18).
__global__ void __launch_bounds__(256)
rowmask_kernel(const float* __restrict__ Z, const int* __restrict__ ids,
               float* __restrict__ outG, float* __restrict__ outZ)
{
    __shared__ float zs[Lsz];
    __shared__ float sf[8], sf2[8];
    __shared__ int   si[8];
    __shared__ unsigned int hist[256];
    __shared__ unsigned int sh_prefix;
    __shared__ int sh_k;
    __shared__ int stotal;
    __shared__ int sbcast;
    __shared__ int wscan[8];

    const int r = blockIdx.x, tid = threadIdx.x;
    const int lane = tid & 31, wid = tid >> 5;
    for (int j = tid; j < Lsz; j += 256) zs[j] = Z[(size_t)r * Lsz + j];
    __syncthreads();

    // phase 1
    float ent = 0.f, dif = 0.f;
    int cnt = 0;
    for (int j = tid; j < Lsz; j += 256) {
        float p = zs[j];
        ent += -(p * logf(__fadd_rn(p, 1e-7f)) +
                 (1.f - p) * logf(__fadd_rn(__fsub_rn(1.f, p), 1e-7f)));
        if (j < Lsz - 1) dif += fabsf(__fsub_rn(zs[j + 1], zs[j])) * g_adj[j];
        if (j < Ssz) {
            int tok = ids[(size_t)r * Ssz + j];
            if (p < 0.5f && tok != 0) cnt++;
        }
    }
#pragma unroll
    for (int o = 16; o > 0; o >>= 1) {
        ent += __shfl_down_sync(0xffffffffu, ent, o);
        dif += __shfl_down_sync(0xffffffffu, dif, o);
        cnt += __shfl_down_sync(0xffffffffu, cnt, o);
    }
    if (lane == 0) { sf[wid] = ent; sf2[wid] = dif; si[wid] = cnt; }
    __syncthreads();
    if (tid == 0) {
        float e = 0.f, d = 0.f; int c = 0;
        for (int i = 0; i < 8; i++) { e += sf[i]; d += sf2[i]; c += si[i]; }
        g_rowEnt[r] = e; g_rowDiff[r] = d; stotal = c;
    }
    __syncthreads();
    const bool needfix = stotal > NEEDFIX_THRESH;

    unsigned int tsel = 0;
    int nEqKeep = 0;
    if (needfix) {
        unsigned int prefix = 0, highmask = 0;
        int k = MINTOK;
        for (int pass = 0; pass < 4; pass++) {
            const int shift = 24 - 8 * pass;
            hist[tid] = 0;
            __syncthreads();
            for (int j = tid; j < Ssz; j += 256) {
                unsigned int key = __float_as_uint(zs[j]);
                if ((key & highmask) == prefix)
                    atomicAdd(&hist[(key >> shift) & 0xFFu], 1u);
            }
            __syncthreads();
            if (tid == 0) {
                int cum = 0, b = 255;
                for (; b >= 0; --b) { cum += (int)hist[b]; if (cum >= k) break; }
                sh_k = k - (cum - (int)hist[b]);
                sh_prefix = prefix | ((unsigned int)b << shift);
            }
            __syncthreads();
            prefix = sh_prefix;
            k = sh_k;
            highmask |= 0xFFu << shift;
            __syncthreads();
        }
        tsel = prefix;
        int cg = 0;
        for (int j = tid; j < Ssz; j += 256)
            if (__float_as_uint(zs[j]) > tsel) cg++;
#pragma unroll
        for (int o = 16; o > 0; o >>= 1) cg += __shfl_down_sync(0xffffffffu, cg, o);
        if (lane == 0) si[wid] = cg;
        __syncthreads();
        if (tid == 0) { int t = 0; for (int i = 0; i < 8; i++) t += si[i]; sbcast = t; }
        __syncthreads();
        nEqKeep = MINTOK - sbcast;   // ties kept lowest-index-first
    }

    // phase 2: thread owns indices [6*tid, 6*tid+6)
    const int jbase = tid * 6;
    float zv[6]; int tok[6];
#pragma unroll
    for (int q = 0; q < 6; q++) {
        zv[q]  = zs[jbase + q];
        tok[q] = ids[(size_t)r * Ssz + jbase + q];
    }
    int eqloc[6];
    int excl = 0;
    if (needfix) {
        int myeq = 0;
#pragma unroll
        for (int q = 0; q < 6; q++) {
            const int eq = (__float_as_uint(zv[q]) == tsel) ? 1 : 0;
            eqloc[q] = myeq;
            myeq += eq;
        }
        int inc = myeq;
#pragma unroll
        for (int o = 1; o < 32; o <<= 1) {
            int t2 = __shfl_up_sync(0xffffffffu, inc, o);
            if (lane >= o) inc += t2;
        }
        excl = inc - myeq;
        if (lane == 31) wscan[wid] = inc;
        __syncthreads();
        if (tid == 0) {
            int run = 0;
            for (int i = 0; i < 8; i++) { int t3 = wscan[i]; wscan[i] = run; run += t3; }
        }
        __syncthreads();
        excl += wscan[wid];
    }
#pragma unroll
    for (int q = 0; q < 6; q++) {
        const int j = jbase + q;
        bool m = (zv[q] < 0.5f) && (tok[q] != 0);
        if (needfix) {
            const unsigned int key = __float_as_uint(zv[q]);
            const bool eq = (key == tsel);
            const bool keep = (key > tsel) || (eq && (excl + eqloc[q]) < nEqKeep);
            if (keep) m = false;
        }
        if (j == 0) m = false;   // applied after keep-adjust, as in reference
        outG[(size_t)r * Ssz + j] = m ? 0.f : (float)tok[q];
        outZ[(size_t)r * Ssz + j] = zv[q];
    }
}

// ---------------- final loss scalar -----------------------------------------
__global__ void finalize_kernel(float* __restrict__ out)
{
    __shared__ double red[256];
    const int tid = threadIdx.x;
    double e = 0, d = 0;
    for (int r = tid; r < Bsz; r += 256) {
        e += (double)g_rowEnt[r];
        d += (double)g_rowDiff[r];
    }
    red[tid] = e; __syncthreads();
    for (int o = 128; o > 0; o >>= 1) { if (tid < o) red[tid] += red[tid + o]; __syncthreads(); }
    const double entSum = red[0];
    __syncthreads();
    red[tid] = d; __syncthreads();
    for (int o = 128; o > 0; o >>= 1) { if (tid < o) red[tid] += red[tid + o]; __syncthreads(); }
    const double difSum = red[0];
    if (tid == 0) {
        double R1 = -0.001 * entSum / ((double)Bsz * (double)Lsz);
        double R2 =  0.001 * difSum / ((double)Bsz * (double)(Lsz - 1));
        double cons = 0.001 * g_cons[0] / (double)Lsz;
        out[(size_t)Bsz * Ssz] = (float)(R1 + R2 + cons);
    }
}

// ---------------- launch ------------------------------------------------------
extern "C" void kernel_launch(void* const* d_in, const int* in_sizes, int n_in,
                              void* d_out, int out_size)
{
    const float* in_g  = (const float*)d_in[0];
    const float* in_b  = (const float*)d_in[1];
    const float* wv    = (const float*)d_in[2];
    const float* bv    = (const float*)d_in[3];
    const float* wo    = (const float*)d_in[4];
    const float* bo    = (const float*)d_in[5];
    const float* w2    = (const float*)d_in[6];
    const float* b2    = (const float*)d_in[7];
    const float* g1    = (const float*)d_in[8];
    const float* be1   = (const float*)d_in[9];
    const float* w4    = (const float*)d_in[10];
    const float* b4    = (const float*)d_in[11];
    const float* g3    = (const float*)d_in[12];
    const float* be3   = (const float*)d_in[13];
    const float* w5    = (const float*)d_in[14];
    const float* b5    = (const float*)d_in[15];
    const float* g4    = (const float*)d_in[16];
    const float* be4   = (const float*)d_in[17];
    const float* w6    = (const float*)d_in[18];
    const float* b6    = (const float*)d_in[19];
    const float* g5    = (const float*)d_in[20];
    const float* be5   = (const float*)d_in[21];
    const float* w7    = (const float*)d_in[22];
    const float* b7    = (const float*)d_in[23];
    const float* g6    = (const float*)d_in[24];
    const float* be6   = (const float*)d_in[25];
    const float* wout  = (const float*)d_in[26];
    const float* bout  = (const float*)d_in[27];
    const float* fe    = (const float*)d_in[28];
    const int*   ids   = (const int*)d_in[29];
    float* out = (float*)d_out;

    float *pA, *pBf, *pC1, *pC2, *pC3, *pD1, *pD2;
    cudaGetSymbolAddress((void**)&pA,  g_A);
    cudaGetSymbolAddress((void**)&pBf, g_Bf);
    cudaGetSymbolAddress((void**)&pC1, g_C1);
    cudaGetSymbolAddress((void**)&pC2, g_C2);
    cudaGetSymbolAddress((void**)&pC3, g_C3);
    cudaGetSymbolAddress((void**)&pD1, g_D1);
    cudaGetSymbolAddress((void**)&pD2, g_D2);

    ln_input_kernel<<<Bsz, 256>>>(ids, in_g, in_b, pA);

    sgemm_nt<<<dim3(Lsz/64, Bsz/128), 256>>>(pA,  wv, bv, pBf, Bsz, Lsz, Lsz);
    sgemm_nt<<<dim3(Lsz/64, Bsz/128), 256>>>(pBf, wo, bo, pA,  Bsz, Lsz, Lsz);

    sgemm_nt<<<dim3(Hsz/64, Bsz/128), 256>>>(pA, w2, b2, pC1, Bsz, Hsz, Lsz);
    ln_gelu_kernel<4><<<Bsz, 256>>>(pC1, g1, be1, pC1, pC2);

    sgemm_nt<<<dim3(Hsz/64, Bsz/128), 256>>>(pC2, w4, b4, pC3, Bsz, Hsz, Hsz);
    ln_gelu_kernel<4><<<Bsz, 256>>>(pC3, g3, be3, nullptr, pC3);

    sgemm_nt<<<dim3(Hsz/64, Bsz/128), 256>>>(pC3, w5, b5, pC1, Bsz, Hsz, Hsz);
    ln_gelu_kernel<4><<<Bsz, 256>>>(pC1, g4, be4, pC2, pC1);

    sgemm_nt<<<dim3((Hsz/2)/64, Bsz/128), 256>>>(pC1, w6, b6, pD1, Bsz, Hsz/2, Hsz);
    ln_gelu_kernel<2><<<Bsz, 256>>>(pD1, g5, be5, nullptr, pD1);

    sgemm_nt<<<dim3((Hsz/4)/64, Bsz/128), 256>>>(pD1, w7, b7, pD2, Bsz, Hsz/4, Hsz/2);
    ln_gelu_kernel<1><<<Bsz, 256>>>(pD2, g6, be6, nullptr, pD2);

    sgemm_nt<<<dim3(Lsz/64, Bsz/128), 256>>>(pD2, wout, bout, pBf, Bsz, Lsz, Hsz/4);
    sigmoid_kernel<<<(Bsz*Lsz)/256, 256>>>(pBf, pA);

    colstats_kernel<<<dim3(Lsz/256, CCH), 256>>>(pA);
    colcombine_kernel<<<Lsz/256, 256>>>();
    adjcons_kernel<<<1, 256>>>(fe);

    rowmask_kernel<<<Bsz, 256>>>(pA, ids, out, out + (size_t)Bsz * Ssz + 1);

    finalize_kernel<<<1, 256>>>(out);
}

// round 13
// speedup vs baseline: 2.3484x; 1.0958x over previous
#include <cuda_runtime.h>
#include <cuda_bf16.h>
#include <math.h>

// Problem constants
#define Bsz 4096
#define Ssz 1536
#define Lsz 2048
#define Hsz 1024
#define MINTOK 460                     // int(0.3*1536)
#define NEEDFIX_THRESH (Ssz - MINTOK)  // 1076

// ---------------- scratch (device globals; no allocations allowed) ----------
__device__ float g_A [(size_t)Bsz * Lsz];
__device__ float g_Bf[(size_t)Bsz * Lsz];
__device__ float g_C1[(size_t)Bsz * Hsz];
__device__ float g_C2[(size_t)Bsz * Hsz];
__device__ float g_C3[(size_t)Bsz * Hsz];
__device__ float g_D1[(size_t)Bsz * (Hsz/2)];
__device__ float g_D2[(size_t)Bsz * (Hsz/4)];

#define CCH 64
__device__ double g_p1[CCH * Lsz];
__device__ double g_p2[CCH * Lsz];
__device__ double g_p3[CCH * Lsz];
__device__ double g_S1[Lsz], g_S2[Lsz], g_S3[Lsz];
__device__ float  g_adj[Lsz];
__device__ float  g_rowEnt[Bsz], g_rowDiff[Bsz];
__device__ double g_cons[1];

// ---- f32x2 packed helpers (PTX-only; each half is an independent IEEE op) --
__device__ __forceinline__ unsigned long long pk2(float lo, float hi) {
    unsigned long long r;
    asm("mov.b64 %0, {%1, %2};" : "=l"(r) : "f"(lo), "f"(hi));
    return r;
}
__device__ __forceinline__ void upk2(unsigned long long v, float& lo, float& hi) {
    asm("mov.b64 {%0, %1}, %2;" : "=f"(lo), "=f"(hi) : "l"(v));
}
__device__ __forceinline__ unsigned long long fma2(unsigned long long a,
                                                   unsigned long long b,
                                                   unsigned long long c) {
    unsigned long long d;
    asm("fma.rn.f32x2 %0, %1, %2, %3;" : "=l"(d) : "l"(a), "l"(b), "l"(c));
    return d;
}

union F4U2 { float4 f; struct { unsigned long long lo, hi; } u; };

__device__ __forceinline__ double warp_rsum_d(double x) {
#pragma unroll
    for (int o = 16; o > 0; o >>= 1)
        x += __shfl_down_sync(0xffffffffu, x, o);
    return x;
}

// ---------------- GEMM: C[M,N] = A[M,K] @ W[N,K]^T + bias[N] ----------------
// Numerics: per output, fp32 FFMA over each ascending 64-k chunk; chunk sums
// folded ascending into an fp32 accumulator (plain add; compensation dropped —
// adds ~2e-7 relative, below the reference-diff floor). f32x2 packs two
// M-adjacent outputs per instruction — identical IEEE arithmetic per output.
// Perf: 128x64 block tile, 8x4/thread, 256 threads, BK=16 double-buffered
// stages + gmem register prefetch. State fits ~120 regs -> 2 CTAs/SM via
// launch_bounds(256,2) (mild cap, no spill expected).
__global__ void __launch_bounds__(256, 2)
sgemm_nt(const float* __restrict__ A, const float* __restrict__ W,
         const float* __restrict__ bias, float* __restrict__ C,
         int M, int N, int K)
{
    constexpr int BK = 16;
    __shared__ float As[2][BK][128];
    __shared__ float Bs[2][BK][64 + 4];
    const int tid = threadIdx.x;
    const int bm = blockIdx.y * 128;
    const int bn = blockIdx.x * 64;
    const int tr = (tid >> 4) << 3;     // 0..120 step 8
    const int tc = (tid & 15) << 2;     // 0..60 step 4

    const int arow = tid & 127;
    const int ak   = (tid >> 7) << 3;   // 0 or 8
    const int brow = tid & 63;
    const int bk   = (tid >> 6) << 2;   // 0,4,8,12

    const float* Ap = A + (size_t)(bm + arow) * K + ak;
    const float* Wp = W + (size_t)(bn + brow) * K + bk;

    unsigned long long facc2[4][4];     // M-pairs (tr+2p, tr+2p+1) x 4 N
    float ksum[8][4];
#pragma unroll
    for (int i = 0; i < 8; i++)
#pragma unroll
        for (int j = 0; j < 4; j++) ksum[i][j] = 0.f;
#pragma unroll
    for (int p = 0; p < 4; p++)
#pragma unroll
        for (int j = 0; j < 4; j++) facc2[p][j] = 0ull;

    const int nch = K / BK;   // 16-k stages; fold every 4 stages (64 k)

    float4 aq0 = *(const float4*)(Ap);
    float4 aq1 = *(const float4*)(Ap + 4);
    float4 bq0 = *(const float4*)(Wp);
    As[0][ak + 0][arow] = aq0.x; As[0][ak + 1][arow] = aq0.y;
    As[0][ak + 2][arow] = aq0.z; As[0][ak + 3][arow] = aq0.w;
    As[0][ak + 4][arow] = aq1.x; As[0][ak + 5][arow] = aq1.y;
    As[0][ak + 6][arow] = aq1.z; As[0][ak + 7][arow] = aq1.w;
    Bs[0][bk + 0][brow] = bq0.x; Bs[0][bk + 1][brow] = bq0.y;
    Bs[0][bk + 2][brow] = bq0.z; Bs[0][bk + 3][brow] = bq0.w;
    __syncthreads();

    for (int c = 0; c < nch; c++) {
        const int buf = c & 1;
        const bool more = (c + 1 < nch);
        if (more) {
            const int k0 = (c + 1) * BK;
            aq0 = *(const float4*)(Ap + k0);
            aq1 = *(const float4*)(Ap + k0 + 4);
            bq0 = *(const float4*)(Wp + k0);
        }

#pragma unroll
        for (int k = 0; k < BK; k++) {
            F4U2 a0, a1;
            a0.f = *(const float4*)(&As[buf][k][tr]);
            a1.f = *(const float4*)(&As[buf][k][tr + 4]);
            const float4 bv = *(const float4*)(&Bs[buf][k][tc]);
            const unsigned long long bb0 = pk2(bv.x, bv.x);
            const unsigned long long bb1 = pk2(bv.y, bv.y);
            const unsigned long long bb2 = pk2(bv.z, bv.z);
            const unsigned long long bb3 = pk2(bv.w, bv.w);
            facc2[0][0] = fma2(a0.u.lo, bb0, facc2[0][0]);
            facc2[0][1] = fma2(a0.u.lo, bb1, facc2[0][1]);
            facc2[0][2] = fma2(a0.u.lo, bb2, facc2[0][2]);
            facc2[0][3] = fma2(a0.u.lo, bb3, facc2[0][3]);
            facc2[1][0] = fma2(a0.u.hi, bb0, facc2[1][0]);
            facc2[1][1] = fma2(a0.u.hi, bb1, facc2[1][1]);
            facc2[1][2] = fma2(a0.u.hi, bb2, facc2[1][2]);
            facc2[1][3] = fma2(a0.u.hi, bb3, facc2[1][3]);
            facc2[2][0] = fma2(a1.u.lo, bb0, facc2[2][0]);
            facc2[2][1] = fma2(a1.u.lo, bb1, facc2[2][1]);
            facc2[2][2] = fma2(a1.u.lo, bb2, facc2[2][2]);
            facc2[2][3] = fma2(a1.u.lo, bb3, facc2[2][3]);
            facc2[3][0] = fma2(a1.u.hi, bb0, facc2[3][0]);
            facc2[3][1] = fma2(a1.u.hi, bb1, facc2[3][1]);
            facc2[3][2] = fma2(a1.u.hi, bb2, facc2[3][2]);
            facc2[3][3] = fma2(a1.u.hi, bb3, facc2[3][3]);
        }

        if ((c & 3) == 3) {
            // plain fp32 fold of the completed 64-k chunk (ascending chunks)
#pragma unroll
            for (int p = 0; p < 4; p++)
#pragma unroll
                for (int j = 0; j < 4; j++) {
                    float flo, fhi;
                    upk2(facc2[p][j], flo, fhi);
                    ksum[2 * p][j]     = __fadd_rn(ksum[2 * p][j], flo);
                    ksum[2 * p + 1][j] = __fadd_rn(ksum[2 * p + 1][j], fhi);
                    facc2[p][j] = 0ull;
                }
        }

        if (more) {
            __syncthreads();
            const int nb = buf ^ 1;
            As[nb][ak + 0][arow] = aq0.x; As[nb][ak + 1][arow] = aq0.y;
            As[nb][ak + 2][arow] = aq0.z; As[nb][ak + 3][arow] = aq0.w;
            As[nb][ak + 4][arow] = aq1.x; As[nb][ak + 5][arow] = aq1.y;
            As[nb][ak + 6][arow] = aq1.z; As[nb][ak + 7][arow] = aq1.w;
            Bs[nb][bk + 0][brow] = bq0.x; Bs[nb][bk + 1][brow] = bq0.y;
            Bs[nb][bk + 2][brow] = bq0.z; Bs[nb][bk + 3][brow] = bq0.w;
            __syncthreads();
        }
    }

    float bj[4];
#pragma unroll
    for (int j = 0; j < 4; j++) bj[j] = bias[bn + tc + j];
#pragma unroll
    for (int i = 0; i < 8; i++) {
        float* Cp = C + (size_t)(bm + tr + i) * N + bn + tc;
        float4 v;
        v.x = __fadd_rn(ksum[i][0], bj[0]);
        v.y = __fadd_rn(ksum[i][1], bj[1]);
        v.z = __fadd_rn(ksum[i][2], bj[2]);
        v.w = __fadd_rn(ksum[i][3], bj[3]);
        *(float4*)Cp = v;
    }
}

// ---------------- LN of padded int input -> X0 ------------------------------
__global__ void __launch_bounds__(256)
ln_input_kernel(const int* __restrict__ ids,
                const float* __restrict__ gam,
                const float* __restrict__ bet,
                float* __restrict__ out)
{
    constexpr int NE = 8;   // 2048 / 256
    __shared__ double sw[8];
    __shared__ double sbc;
    const int r = blockIdx.x, tid = threadIdx.x;
    float v[NE];
#pragma unroll
    for (int i = 0; i < NE; i++) {
        const int j = tid + (i << 8);
        v[i] = (j < Ssz) ? (float)ids[(size_t)r * Ssz + j] : 0.f;
    }
    double p = 0.0;
#pragma unroll
    for (int i = 0; i < NE; i++) p += (double)v[i];
    double ws = warp_rsum_d(p);
    if ((tid & 31) == 0) sw[tid >> 5] = ws;
    __syncthreads();
    if (tid == 0) { double t = 0; for (int i = 0; i < 8; i++) t += sw[i]; sbc = t; }
    __syncthreads();
    const double mean = sbc / (double)Lsz;
    const float  mf   = (float)mean;
    double vv = 0.0;
#pragma unroll
    for (int i = 0; i < NE; i++) { double d = (double)v[i] - mean; vv += d * d; }
    ws = warp_rsum_d(vv);
    __syncthreads();
    if ((tid & 31) == 0) sw[tid >> 5] = ws;
    __syncthreads();
    if (tid == 0) { double t = 0; for (int i = 0; i < 8; i++) t += sw[i]; sbc = t; }
    __syncthreads();
    const float vf  = (float)(sbc / (double)Lsz);
    const float arg = __fadd_rn(vf, 1e-5f);
    const float rs  = (float)(1.0 / sqrt((double)arg));
#pragma unroll
    for (int i = 0; i < NE; i++) {
        const int j = tid + (i << 8);
        float t = __fmul_rn(__fmul_rn(__fsub_rn(v[i], mf), rs), gam[j]);
        out[(size_t)r * Lsz + j] = __fadd_rn(t, bet[j]);
    }
}

// ---------------- LN + exact GELU (+ optional residual), per row ------------
template<int NE>
__global__ void __launch_bounds__(256)
ln_gelu_kernel(const float* __restrict__ in,
               const float* __restrict__ gam,
               const float* __restrict__ bet,
               const float* __restrict__ res,
               float* __restrict__ out)
{
    constexpr int n = NE * 256;
    __shared__ double sw[8];
    __shared__ double sbc;
    const int r = blockIdx.x, tid = threadIdx.x;
    float v[NE];
#pragma unroll
    for (int i = 0; i < NE; i++) v[i] = in[(size_t)r * n + tid + (i << 8)];
    double p = 0.0;
#pragma unroll
    for (int i = 0; i < NE; i++) p += (double)v[i];
    double ws = warp_rsum_d(p);
    if ((tid & 31) == 0) sw[tid >> 5] = ws;
    __syncthreads();
    if (tid == 0) { double t = 0; for (int i = 0; i < 8; i++) t += sw[i]; sbc = t; }
    __syncthreads();
    const double mean = sbc / (double)n;
    const float  mf   = (float)mean;
    double vv = 0.0;
#pragma unroll
    for (int i = 0; i < NE; i++) { double d = (double)v[i] - mean; vv += d * d; }
    ws = warp_rsum_d(vv);
    __syncthreads();
    if ((tid & 31) == 0) sw[tid >> 5] = ws;
    __syncthreads();
    if (tid == 0) { double t = 0; for (int i = 0; i < 8; i++) t += sw[i]; sbc = t; }
    __syncthreads();
    const float vf  = (float)(sbc / (double)n);
    const float arg = __fadd_rn(vf, 1e-5f);
    const float rs  = (float)(1.0 / sqrt((double)arg));
#pragma unroll
    for (int i = 0; i < NE; i++) {
        const int j = tid + (i << 8);
        float x = __fadd_rn(__fmul_rn(__fmul_rn(__fsub_rn(v[i], mf), rs), gam[j]), bet[j]);
        float u = __fmul_rn(x, 0.70710678118654752f);
        float e = erff(u);
        float ge = __fmul_rn(__fmul_rn(x, __fadd_rn(e, 1.f)), 0.5f);
        float o = res ? __fadd_rn(ge, res[(size_t)r * n + j]) : ge;
        out[(size_t)r * n + j] = o;
    }
}

// ---------------- mu -> z = sigmoid(clip(mu,-5,5)), exact -------------------
__global__ void sigmoid_kernel(const float* __restrict__ mu, float* __restrict__ z)
{
    size_t i = (size_t)blockIdx.x * 256 + threadIdx.x;
    if (i < (size_t)Bsz * Lsz) {
        float m = mu[i];
        m = fminf(5.f, fmaxf(-5.f, m));
        z[i] = (float)(1.0 / (1.0 + exp(-(double)m)));
    }
}

// ---------------- column stats ----------------------------------------------
__global__ void colstats_kernel(const float* __restrict__ Z)
{
    const int j  = blockIdx.x * 256 + threadIdx.x;
    const int ch = blockIdx.y;
    const int r0 = ch * (Bsz / CCH);
    const bool hasN = (j < Lsz - 1);
    double s1 = 0, s2 = 0, s3 = 0;
    for (int r = r0; r < r0 + (Bsz / CCH); ++r) {
        float z  = Z[(size_t)r * Lsz + j];
        float zn = hasN ? Z[(size_t)r * Lsz + j + 1] : 0.f;
        s1 += (double)z;
        s2 += (double)z * (double)z;
        s3 += (double)z * (double)zn;
    }
    g_p1[ch * Lsz + j] = s1;
    g_p2[ch * Lsz + j] = s2;
    g_p3[ch * Lsz + j] = s3;
}

__global__ void colcombine_kernel()
{
    const int j = blockIdx.x * 256 + threadIdx.x;
    double s1 = 0, s2 = 0, s3 = 0;
    for (int c = 0; c < CCH; c++) {
        s1 += g_p1[c * Lsz + j];
        s2 += g_p2[c * Lsz + j];
        s3 += g_p3[c * Lsz + j];
    }
    g_S1[j] = s1; g_S2[j] = s2; g_S3[j] = s3;
}

// ---------------- adj (corr>0.5) + consistency term -------------------------
__global__ void adjcons_kernel(const float* __restrict__ fe)
{
    __shared__ double red[256];
    const int tid = threadIdx.x;
    double cons = 0.0;
    for (int j = tid; j < Lsz; j += 256) {
        double m = g_S1[j] / (double)Bsz;
        cons += fabs(m - (double)fe[j]);
        if (j < Lsz - 1) {
            double cov = g_S3[j] - g_S1[j] * g_S1[j + 1] / (double)Bsz;
            double v1  = g_S2[j]     - g_S1[j]     * g_S1[j]     / (double)Bsz;
            double v2  = g_S2[j + 1] - g_S1[j + 1] * g_S1[j + 1] / (double)Bsz;
            double den = v1 * v2;
            float a = 0.f;
            if (den > 0.0 && cov / sqrt(den) > 0.5) a = 1.f;
            g_adj[j] = a;
        }
    }
    red[tid] = cons; __syncthreads();
    for (int o = 128; o > 0; o >>= 1) { if (tid < o) red[tid] += red[tid + o]; __syncthreads(); }
    if (tid == 0) g_cons[0] = red[0];
}

// ---------------- per-row mask / top-k / outputs -----------------------------
__global__ void __launch_bounds__(256)
rowmask_kernel(const float* __restrict__ Z, const int* __restrict__ ids,
               float* __restrict__ outG, float* __restrict__ outZ)
{
    __shared__ float zs[Lsz];
    __shared__ float sf[8], sf2[8];
    __shared__ int   si[8];
    __shared__ unsigned int hist[256];
    __shared__ unsigned int sh_prefix;
    __shared__ int sh_k;
    __shared__ int stotal;
    __shared__ int sbcast;
    __shared__ int wscan[8];

    const int r = blockIdx.x, tid = threadIdx.x;
    const int lane = tid & 31, wid = tid >> 5;
    for (int j = tid; j < Lsz; j += 256) zs[j] = Z[(size_t)r * Lsz + j];
    __syncthreads();

    // phase 1
    float ent = 0.f, dif = 0.f;
    int cnt = 0;
    for (int j = tid; j < Lsz; j += 256) {
        float p = zs[j];
        ent += -(p * logf(__fadd_rn(p, 1e-7f)) +
                 (1.f - p) * logf(__fadd_rn(__fsub_rn(1.f, p), 1e-7f)));
        if (j < Lsz - 1) dif += fabsf(__fsub_rn(zs[j + 1], zs[j])) * g_adj[j];
        if (j < Ssz) {
            int tok = ids[(size_t)r * Ssz + j];
            if (p < 0.5f && tok != 0) cnt++;
        }
    }
#pragma unroll
    for (int o = 16; o > 0; o >>= 1) {
        ent += __shfl_down_sync(0xffffffffu, ent, o);
        dif += __shfl_down_sync(0xffffffffu, dif, o);
        cnt += __shfl_down_sync(0xffffffffu, cnt, o);
    }
    if (lane == 0) { sf[wid] = ent; sf2[wid] = dif; si[wid] = cnt; }
    __syncthreads();
    if (tid == 0) {
        float e = 0.f, d = 0.f; int c = 0;
        for (int i = 0; i < 8; i++) { e += sf[i]; d += sf2[i]; c += si[i]; }
        g_rowEnt[r] = e; g_rowDiff[r] = d; stotal = c;
    }
    __syncthreads();
    const bool needfix = stotal > NEEDFIX_THRESH;

    unsigned int tsel = 0;
    int nEqKeep = 0;
    if (needfix) {
        unsigned int prefix = 0, highmask = 0;
        int k = MINTOK;
        for (int pass = 0; pass < 4; pass++) {
            const int shift = 24 - 8 * pass;
            hist[tid] = 0;
            __syncthreads();
            for (int j = tid; j < Ssz; j += 256) {
                unsigned int key = __float_as_uint(zs[j]);
                if ((key & highmask) == prefix)
                    atomicAdd(&hist[(key >> shift) & 0xFFu], 1u);
            }
            __syncthreads();
            if (tid == 0) {
                int cum = 0, b = 255;
                for (; b >= 0; --b) { cum += (int)hist[b]; if (cum >= k) break; }
                sh_k = k - (cum - (int)hist[b]);
                sh_prefix = prefix | ((unsigned int)b << shift);
            }
            __syncthreads();
            prefix = sh_prefix;
            k = sh_k;
            highmask |= 0xFFu << shift;
            __syncthreads();
        }
        tsel = prefix;
        int cg = 0;
        for (int j = tid; j < Ssz; j += 256)
            if (__float_as_uint(zs[j]) > tsel) cg++;
#pragma unroll
        for (int o = 16; o > 0; o >>= 1) cg += __shfl_down_sync(0xffffffffu, cg, o);
        if (lane == 0) si[wid] = cg;
        __syncthreads();
        if (tid == 0) { int t = 0; for (int i = 0; i < 8; i++) t += si[i]; sbcast = t; }
        __syncthreads();
        nEqKeep = MINTOK - sbcast;   // ties kept lowest-index-first
    }

    // phase 2: thread owns indices [6*tid, 6*tid+6)
    const int jbase = tid * 6;
    float zv[6]; int tok[6];
#pragma unroll
    for (int q = 0; q < 6; q++) {
        zv[q]  = zs[jbase + q];
        tok[q] = ids[(size_t)r * Ssz + jbase + q];
    }
    int eqloc[6];
    int excl = 0;
    if (needfix) {
        int myeq = 0;
#pragma unroll
        for (int q = 0; q < 6; q++) {
            const int eq = (__float_as_uint(zv[q]) == tsel) ? 1 : 0;
            eqloc[q] = myeq;
            myeq += eq;
        }
        int inc = myeq;
#pragma unroll
        for (int o = 1; o < 32; o <<= 1) {
            int t2 = __shfl_up_sync(0xffffffffu, inc, o);
            if (lane >= o) inc += t2;
        }
        excl = inc - myeq;
        if (lane == 31) wscan[wid] = inc;
        __syncthreads();
        if (tid == 0) {
            int run = 0;
            for (int i = 0; i < 8; i++) { int t3 = wscan[i]; wscan[i] = run; run += t3; }
        }
        __syncthreads();
        excl += wscan[wid];
    }
#pragma unroll
    for (int q = 0; q < 6; q++) {
        const int j = jbase + q;
        bool m = (zv[q] < 0.5f) && (tok[q] != 0);
        if (needfix) {
            const unsigned int key = __float_as_uint(zv[q]);
            const bool eq = (key == tsel);
            const bool keep = (key > tsel) || (eq && (excl + eqloc[q]) < nEqKeep);
            if (keep) m = false;
        }
        if (j == 0) m = false;   // applied after keep-adjust, as in reference
        outG[(size_t)r * Ssz + j] = m ? 0.f : (float)tok[q];
        outZ[(size_t)r * Ssz + j] = zv[q];
    }
}

// ---------------- final loss scalar -----------------------------------------
__global__ void finalize_kernel(float* __restrict__ out)
{
    __shared__ double red[256];
    const int tid = threadIdx.x;
    double e = 0, d = 0;
    for (int r = tid; r < Bsz; r += 256) {
        e += (double)g_rowEnt[r];
        d += (double)g_rowDiff[r];
    }
    red[tid] = e; __syncthreads();
    for (int o = 128; o > 0; o >>= 1) { if (tid < o) red[tid] += red[tid + o]; __syncthreads(); }
    const double entSum = red[0];
    __syncthreads();
    red[tid] = d; __syncthreads();
    for (int o = 128; o > 0; o >>= 1) { if (tid < o) red[tid] += red[tid + o]; __syncthreads(); }
    const double difSum = red[0];
    if (tid == 0) {
        double R1 = -0.001 * entSum / ((double)Bsz * (double)Lsz);
        double R2 =  0.001 * difSum / ((double)Bsz * (double)(Lsz - 1));
        double cons = 0.001 * g_cons[0] / (double)Lsz;
        out[(size_t)Bsz * Ssz] = (float)(R1 + R2 + cons);
    }
}

// ---------------- launch ------------------------------------------------------
extern "C" void kernel_launch(void* const* d_in, const int* in_sizes, int n_in,
                              void* d_out, int out_size)
{
    const float* in_g  = (const float*)d_in[0];
    const float* in_b  = (const float*)d_in[1];
    const float* wv    = (const float*)d_in[2];
    const float* bv    = (const float*)d_in[3];
    const float* wo    = (const float*)d_in[4];
    const float* bo    = (const float*)d_in[5];
    const float* w2    = (const float*)d_in[6];
    const float* b2    = (const float*)d_in[7];
    const float* g1    = (const float*)d_in[8];
    const float* be1   = (const float*)d_in[9];
    const float* w4    = (const float*)d_in[10];
    const float* b4    = (const float*)d_in[11];
    const float* g3    = (const float*)d_in[12];
    const float* be3   = (const float*)d_in[13];
    const float* w5    = (const float*)d_in[14];
    const float* b5    = (const float*)d_in[15];
    const float* g4    = (const float*)d_in[16];
    const float* be4   = (const float*)d_in[17];
    const float* w6    = (const float*)d_in[18];
    const float* b6    = (const float*)d_in[19];
    const float* g5    = (const float*)d_in[20];
    const float* be5   = (const float*)d_in[21];
    const float* w7    = (const float*)d_in[22];
    const float* b7    = (const float*)d_in[23];
    const float* g6    = (const float*)d_in[24];
    const float* be6   = (const float*)d_in[25];
    const float* wout  = (const float*)d_in[26];
    const float* bout  = (const float*)d_in[27];
    const float* fe    = (const float*)d_in[28];
    const int*   ids   = (const int*)d_in[29];
    float* out = (float*)d_out;

    float *pA, *pBf, *pC1, *pC2, *pC3, *pD1, *pD2;
    cudaGetSymbolAddress((void**)&pA,  g_A);
    cudaGetSymbolAddress((void**)&pBf, g_Bf);
    cudaGetSymbolAddress((void**)&pC1, g_C1);
    cudaGetSymbolAddress((void**)&pC2, g_C2);
    cudaGetSymbolAddress((void**)&pC3, g_C3);
    cudaGetSymbolAddress((void**)&pD1, g_D1);
    cudaGetSymbolAddress((void**)&pD2, g_D2);

    ln_input_kernel<<<Bsz, 256>>>(ids, in_g, in_b, pA);

    sgemm_nt<<<dim3(Lsz/64, Bsz/128), 256>>>(pA,  wv, bv, pBf, Bsz, Lsz, Lsz);
    sgemm_nt<<<dim3(Lsz/64, Bsz/128), 256>>>(pBf, wo, bo, pA,  Bsz, Lsz, Lsz);

    sgemm_nt<<<dim3(Hsz/64, Bsz/128), 256>>>(pA, w2, b2, pC1, Bsz, Hsz, Lsz);
    ln_gelu_kernel<4><<<Bsz, 256>>>(pC1, g1, be1, pC1, pC2);

    sgemm_nt<<<dim3(Hsz/64, Bsz/128), 256>>>(pC2, w4, b4, pC3, Bsz, Hsz, Hsz);
    ln_gelu_kernel<4><<<Bsz, 256>>>(pC3, g3, be3, nullptr, pC3);

    sgemm_nt<<<dim3(Hsz/64, Bsz/128), 256>>>(pC3, w5, b5, pC1, Bsz, Hsz, Hsz);
    ln_gelu_kernel<4><<<Bsz, 256>>>(pC1, g4, be4, pC2, pC1);

    sgemm_nt<<<dim3((Hsz/2)/64, Bsz/128), 256>>>(pC1, w6, b6, pD1, Bsz, Hsz/2, Hsz);
    ln_gelu_kernel<2><<<Bsz, 256>>>(pD1, g5, be5, nullptr, pD1);

    sgemm_nt<<<dim3((Hsz/4)/64, Bsz/128), 256>>>(pD1, w7, b7, pD2, Bsz, Hsz/4, Hsz/2);
    ln_gelu_kernel<1><<<Bsz, 256>>>(pD2, g6, be6, nullptr, pD2);

    sgemm_nt<<<dim3(Lsz/64, Bsz/128), 256>>>(pD2, wout, bout, pBf, Bsz, Lsz, Hsz/4);
    sigmoid_kernel<<<(Bsz*Lsz)/256, 256>>>(pBf, pA);

    colstats_kernel<<<dim3(Lsz/256, CCH), 256>>>(pA);
    colcombine_kernel<<<Lsz/256, 256>>>();
    adjcons_kernel<<<1, 256>>>(fe);

    rowmask_kernel<<<Bsz, 256>>>(pA, ids, out, out + (size_t)Bsz * Ssz + 1);

    finalize_kernel<<<1, 256>>>(out);
}